// round 14
// baseline (speedup 1.0000x reference)
#include <cuda_runtime.h>
#include <cuda_bf16.h>
#include <math_constants.h>

#define NN 20000
#define EE 320000
#define ET (EE + NN)
#define HC 256

// ---------------- scratch (device globals; no allocation) ----------------
__device__ float g_sl[(size_t)NN * 8];          // self-loop edge attrs
__device__ float g_xl[(size_t)NN * HC];         // source transform (fp32)
__device__ float g_xr[(size_t)NN * HC];         // dest transform   (fp32)
__device__ __nv_bfloat16 g_ah[(size_t)NN * HC]; // node features hi
__device__ __nv_bfloat16 g_al[(size_t)NN * HC]; // node features lo
__device__ __nv_bfloat16 g_wh[4][HC * HC];      // transposed weight hi  [n][k]
__device__ __nv_bfloat16 g_wl[4][HC * HC];      // transposed weight lo  [n][k]
__device__ int   g_deg[NN];
__device__ int   g_fill[NN];
__device__ int   g_rowptr[NN + 1];
__device__ int   g_eid[ET];
__device__ int   g_esrc[ET];

typedef unsigned long long ull;

__device__ __forceinline__ void splitf(float v, __nv_bfloat16& h, __nv_bfloat16& l) {
    h = __float2bfloat16(v);
    l = __float2bfloat16(v - __bfloat162float(h));
}

// ---- f32x2 packed helpers ----
__device__ __forceinline__ ull dup2(float s) {
    ull r; asm("mov.b64 %0, {%1, %1};" : "=l"(r) : "f"(s)); return r;
}
__device__ __forceinline__ ull fma2(ull a, ull b, ull c) {
    ull r; asm("fma.rn.f32x2 %0, %1, %2, %3;" : "=l"(r) : "l"(a), "l"(b), "l"(c)); return r;
}
__device__ __forceinline__ ull mul2(ull a, ull b) {
    ull r; asm("mul.rn.f32x2 %0, %1, %2;" : "=l"(r) : "l"(a), "l"(b)); return r;
}
__device__ __forceinline__ ull add2(ull a, ull b) {
    ull r; asm("add.rn.f32x2 %0, %1, %2;" : "=l"(r) : "l"(a), "l"(b)); return r;
}
__device__ __forceinline__ ull abs2(ull a) {
    ull r; asm("and.b64 %0, %1, 0x7FFFFFFF7FFFFFFF;" : "=l"(r) : "l"(a)); return r;
}
__device__ __forceinline__ void unpack2(ull v, float& lo, float& hi) {
    asm("mov.b64 {%0, %1}, %2;" : "=f"(lo), "=f"(hi) : "l"(v));
}

// ---- ldmatrix / cp.async ----
__device__ __forceinline__ void ldsm4(unsigned& r0, unsigned& r1, unsigned& r2, unsigned& r3,
                                      unsigned addr) {
    asm volatile("ldmatrix.sync.aligned.m8n8.x4.shared.b16 {%0,%1,%2,%3}, [%4];"
                 : "=r"(r0), "=r"(r1), "=r"(r2), "=r"(r3) : "r"(addr));
}
__device__ __forceinline__ void cpa16(unsigned sa, const void* ga, int srcbytes) {
    asm volatile("cp.async.ca.shared.global [%0], [%1], 16, %2;"
                 :: "r"(sa), "l"(ga), "r"(srcbytes));
}
#define CP_COMMIT() asm volatile("cp.async.commit_group;")
#define CP_WAIT0()  asm volatile("cp.async.wait_group 0;")
#define CP_WAIT3()  asm volatile("cp.async.wait_group 3;")

// ---------------- weight split + transpose ----------------
__global__ void k_splitw(const float* __restrict__ Wa, const float* __restrict__ Wb,
                         const float* __restrict__ Wc, const float* __restrict__ Wd) {
    const float* W = (blockIdx.z == 0) ? Wa : (blockIdx.z == 1) ? Wb
                   : (blockIdx.z == 2) ? Wc : Wd;
    int idx = blockIdx.x * blockDim.x + threadIdx.x;
    int k = idx >> 8, n = idx & 255;
    float v = W[idx];
    __nv_bfloat16 h, l;
    splitf(v, h, l);
    g_wh[blockIdx.z][n * HC + k] = h;
    g_wl[blockIdx.z][n * HC + k] = l;
}

// ---------------- CSR build ----------------
__global__ void k_zero_init() {
    int i = blockIdx.x * blockDim.x + threadIdx.x;
    if (i < NN) { g_deg[i] = 0; g_fill[i] = 0; }
}

__global__ void k_count(const int* __restrict__ dst) {
    int e = blockIdx.x * blockDim.x + threadIdx.x;
    if (e < EE) atomicAdd(&g_deg[dst[e]], 1);
}

#define NCHUNK 20
__global__ void __launch_bounds__(1024) k_scan() {
    __shared__ int wsum[32];
    __shared__ int woff[32];
    __shared__ int s_carry;
    int tid = threadIdx.x, lane = tid & 31, wid = tid >> 5;
    int v[NCHUNK];
#pragma unroll
    for (int j = 0; j < NCHUNK; ++j) {
        int i = j * 1024 + tid;
        v[j] = (i < NN) ? (g_deg[i] + 1) : 0;
    }
    if (tid == 0) { g_rowptr[0] = 0; s_carry = 0; }
    __syncthreads();
#pragma unroll
    for (int j = 0; j < NCHUNK; ++j) {
        int x = v[j];
#pragma unroll
        for (int off = 1; off < 32; off <<= 1) {
            int t = __shfl_up_sync(0xffffffffu, x, off);
            if (lane >= off) x += t;
        }
        if (lane == 31) wsum[wid] = x;
        __syncthreads();
        if (wid == 0) {
            int s = wsum[lane];
            int y = s;
#pragma unroll
            for (int off = 1; off < 32; off <<= 1) {
                int t = __shfl_up_sync(0xffffffffu, y, off);
                if (lane >= off) y += t;
            }
            woff[lane] = y - s;
        }
        __syncthreads();
        int incl = x + woff[wid] + s_carry;
        int i = j * 1024 + tid;
        if (i < NN) g_rowptr[i + 1] = incl;
        __syncthreads();
        if (tid == 1023) s_carry = incl;
        __syncthreads();
    }
}

__global__ void k_scatter(const int* __restrict__ src, const int* __restrict__ dst) {
    int e = blockIdx.x * blockDim.x + threadIdx.x;
    if (e >= ET) return;
    int s, d;
    if (e < EE) { s = src[e]; d = dst[e]; }
    else        { s = e - EE; d = s; }
    int pos = g_rowptr[d] + atomicAdd(&g_fill[d], 1);
    g_eid[pos]  = e;
    g_esrc[pos] = s;
}

// self-loop attr = mean of incoming edge attrs (warp per node, no atomics)
__global__ void __launch_bounds__(256) k_slmean(const float* __restrict__ eattr) {
    int gw = (blockIdx.x * blockDim.x + threadIdx.x) >> 5;
    int lane = threadIdx.x & 31;
    if (gw >= NN) return;
    int beg = g_rowptr[gw], end = g_rowptr[gw + 1];
    int slot = lane >> 3, ch = lane & 7;
    float v = 0.f;
    for (int p = beg + slot; p < end; p += 4) {
        int eid = g_eid[p];
        if (eid < EE) v += eattr[(size_t)eid * 8 + ch];
    }
    v += __shfl_xor_sync(0xffffffffu, v, 8);
    v += __shfl_xor_sync(0xffffffffu, v, 16);
    if (lane < 8) {
        int dg = end - beg - 1;
        float inv = 1.f / (float)(dg > 1 ? dg : 1);
        g_sl[(size_t)gw * 8 + lane] = v * inv;
    }
}

// ---------------- fp32 GEMM (layer 0 only, K=16), xl+xr fused via z ----------------
#define BM 128
#define BN 128
#define BK 16
__global__ void __launch_bounds__(256) k_gemm(
    const float* __restrict__ A,
    const float* __restrict__ W0, const float* __restrict__ b0,
    const float* __restrict__ W1, const float* __restrict__ b1) {
    __shared__ float As[BK][BM + 4];
    __shared__ float Bs[BK][BN];
    const float* W    = blockIdx.z ? W1 : W0;
    const float* bias = blockIdx.z ? b1 : b0;
    float* O          = blockIdx.z ? g_xr : g_xl;
    const int K = 16;
    int tid = threadIdx.x;
    int tx = tid & 15, ty = tid >> 4;
    int row0 = blockIdx.x * BM;
    int col0 = blockIdx.y * BN;
    float acc[8][8];
#pragma unroll
    for (int i = 0; i < 8; ++i)
#pragma unroll
        for (int j = 0; j < 8; ++j) acc[i][j] = 0.f;

#pragma unroll
    for (int i = 0; i < 2; ++i) {
        int f = tid * 2 + i;
        int r = f >> 2, c4 = (f & 3) * 4;
        int gr = row0 + r;
        float4 v = make_float4(0.f, 0.f, 0.f, 0.f);
        if (gr < NN) v = *reinterpret_cast<const float4*>(&A[(size_t)gr * K + c4]);
        As[c4 + 0][r] = v.x; As[c4 + 1][r] = v.y;
        As[c4 + 2][r] = v.z; As[c4 + 3][r] = v.w;
    }
#pragma unroll
    for (int i = 0; i < 2; ++i) {
        int f = tid * 2 + i;
        int r = f >> 5, c4 = (f & 31) * 4;
        *reinterpret_cast<float4*>(&Bs[r][c4]) =
            *reinterpret_cast<const float4*>(&W[(size_t)r * HC + col0 + c4]);
    }
    __syncthreads();
#pragma unroll
    for (int kk = 0; kk < BK; ++kk) {
        float a[8], b[8];
        *reinterpret_cast<float4*>(&a[0]) = *reinterpret_cast<float4*>(&As[kk][ty * 8]);
        *reinterpret_cast<float4*>(&a[4]) = *reinterpret_cast<float4*>(&As[kk][ty * 8 + 4]);
        *reinterpret_cast<float4*>(&b[0]) = *reinterpret_cast<float4*>(&Bs[kk][tx * 8]);
        *reinterpret_cast<float4*>(&b[4]) = *reinterpret_cast<float4*>(&Bs[kk][tx * 8 + 4]);
#pragma unroll
        for (int i = 0; i < 8; ++i)
#pragma unroll
            for (int j = 0; j < 8; ++j)
                acc[i][j] = fmaf(a[i], b[j], acc[i][j]);
    }
#pragma unroll
    for (int i = 0; i < 8; ++i) {
        int gr = row0 + ty * 8 + i;
        if (gr >= NN) continue;
#pragma unroll
        for (int j4 = 0; j4 < 2; ++j4) {
            int c = col0 + tx * 8 + j4 * 4;
            float4 o;
            o.x = acc[i][j4 * 4 + 0] + bias[c + 0];
            o.y = acc[i][j4 * 4 + 1] + bias[c + 1];
            o.z = acc[i][j4 * 4 + 2] + bias[c + 2];
            o.w = acc[i][j4 * 4 + 3] + bias[c + 3];
            *reinterpret_cast<float4*>(&O[(size_t)gr * HC + c]) = o;
        }
    }
}

// ---------------- split-bf16 tensor-core GEMM, cp.async double-buffered ----------------
#define GBM 64
#define GBN 128
#define GKB 32
#define AST 40
#define NIT (HC / GKB)
#define SZ_A (2 * GBM * AST)
#define SZ_B (2 * GBN * AST)
#define SMEM_MMA ((2 * SZ_A + 2 * SZ_B) * 2)

__device__ __forceinline__ void mma16816(float* c, const unsigned* a, const unsigned* b) {
    asm volatile(
        "mma.sync.aligned.m16n8k16.row.col.f32.bf16.bf16.f32 "
        "{%0,%1,%2,%3}, {%4,%5,%6,%7}, {%8,%9}, {%0,%1,%2,%3};\n"
        : "+f"(c[0]), "+f"(c[1]), "+f"(c[2]), "+f"(c[3])
        : "r"(a[0]), "r"(a[1]), "r"(a[2]), "r"(a[3]), "r"(b[0]), "r"(b[1]));
}

__global__ void __launch_bounds__(256) k_gemm_mma(
    int matbase,
    const float* __restrict__ b0, const float* __restrict__ b1) {
    extern __shared__ __nv_bfloat16 dyn[];
    int mat = matbase + blockIdx.z;
    const float* bias = blockIdx.z ? b1 : b0;
    float* O          = blockIdx.z ? g_xr : g_xl;
    const __nv_bfloat16* Wh = g_wh[mat];
    const __nv_bfloat16* Wl = g_wl[mat];

    unsigned base   = (unsigned)__cvta_generic_to_shared(dyn);
    unsigned addrAh = base;
    unsigned addrAl = addrAh + SZ_A * 2;
    unsigned addrBh = addrAl + SZ_A * 2;
    unsigned addrBl = addrBh + SZ_B * 2;

    int tid = threadIdx.x;
    int warp = tid >> 5, lane = tid & 31;
    int wm = (warp >> 2) * 32;
    int wn = (warp & 3) * 32;
    int row0 = blockIdx.x * GBM;
    int col0 = blockIdx.y * GBN;
    int group = lane >> 2, tg = lane & 3;

    int st_m  = tid >> 2, st_c8 = (tid & 3) * 8;
    int st_gr = row0 + st_m;
    int st_grc = st_gr < NN ? st_gr : 0;
    int st_sb  = (st_gr < NN) ? 16 : 0;

    int a_row = lane & 15;
    int a_k   = (lane >> 4) * 8;
    int b_n   = (lane & 7) + ((lane >> 4) & 1) * 8;
    int b_k   = ((lane >> 3) & 1) * 8;

    float acc[2][4][4];
#pragma unroll
    for (int mt = 0; mt < 2; ++mt)
#pragma unroll
        for (int nt = 0; nt < 4; ++nt)
#pragma unroll
            for (int q = 0; q < 4; ++q) acc[mt][nt][q] = 0.f;

    auto stage = [&](int k0, int buf) {
        unsigned da = (unsigned)(((buf * GBM + st_m) * AST + st_c8) * 2);
        cpa16(addrAh + da, &g_ah[(size_t)st_grc * HC + k0 + st_c8], st_sb);
        cpa16(addrAl + da, &g_al[(size_t)st_grc * HC + k0 + st_c8], st_sb);
#pragma unroll
        for (int t = 0; t < 2; ++t) {
            int idx = tid + t * 256;
            int n = idx >> 2, c8 = (idx & 3) * 8;
            size_t off = (size_t)(col0 + n) * HC + k0 + c8;
            unsigned db = (unsigned)(((buf * GBN + n) * AST + c8) * 2);
            cpa16(addrBh + db, &Wh[off], 16);
            cpa16(addrBl + db, &Wl[off], 16);
        }
        CP_COMMIT();
    };

    stage(0, 0);
    int cur = 0;
    for (int it = 0; it < NIT; ++it) {
        CP_WAIT0();
        __syncthreads();
        if (it + 1 < NIT) stage((it + 1) * GKB, cur ^ 1);
#pragma unroll
        for (int kk = 0; kk < GKB; kk += 16) {
            unsigned ah[2][4], al[2][4];
#pragma unroll
            for (int mt = 0; mt < 2; ++mt) {
                unsigned offA = (unsigned)((((cur * GBM) + wm + mt * 16 + a_row) * AST + kk + a_k) * 2);
                ldsm4(ah[mt][0], ah[mt][1], ah[mt][2], ah[mt][3], addrAh + offA);
                ldsm4(al[mt][0], al[mt][1], al[mt][2], al[mt][3], addrAl + offA);
            }
            unsigned bh[4][2], bl[4][2];
#pragma unroll
            for (int pr = 0; pr < 2; ++pr) {
                unsigned offB = (unsigned)((((cur * GBN) + wn + pr * 16 + b_n) * AST + kk + b_k) * 2);
                ldsm4(bh[2 * pr][0], bh[2 * pr][1], bh[2 * pr + 1][0], bh[2 * pr + 1][1],
                      addrBh + offB);
                ldsm4(bl[2 * pr][0], bl[2 * pr][1], bl[2 * pr + 1][0], bl[2 * pr + 1][1],
                      addrBl + offB);
            }
#pragma unroll
            for (int mt = 0; mt < 2; ++mt)
#pragma unroll
                for (int nt = 0; nt < 4; ++nt) {
                    mma16816(acc[mt][nt], ah[mt], bh[nt]);
                    mma16816(acc[mt][nt], ah[mt], bl[nt]);
                    mma16816(acc[mt][nt], al[mt], bh[nt]);
                }
        }
        __syncthreads();
        cur ^= 1;
    }
#pragma unroll
    for (int mt = 0; mt < 2; ++mt) {
#pragma unroll
        for (int nt = 0; nt < 4; ++nt) {
            int n = col0 + wn + nt * 8 + tg * 2;
            float2 bb = *reinterpret_cast<const float2*>(&bias[n]);
            int m = row0 + wm + mt * 16 + group;
            if (m < NN) {
                float2 o = make_float2(acc[mt][nt][0] + bb.x, acc[mt][nt][1] + bb.y);
                *reinterpret_cast<float2*>(&O[(size_t)m * HC + n]) = o;
            }
            int m2 = m + 8;
            if (m2 < NN) {
                float2 o = make_float2(acc[mt][nt][2] + bb.x, acc[mt][nt][3] + bb.y);
                *reinterpret_cast<float2*>(&O[(size_t)m2 * HC + n]) = o;
            }
        }
    }
}

// ---------------- fused GATv2 attention: warp/node + cp.async 4-deep edge ring ----------------
__global__ void __launch_bounds__(128) k_attn(
    const float* __restrict__ eattr,
    const float* __restrict__ We, const float* __restrict__ att,
    const float* __restrict__ bias) {
    __shared__ __align__(16) float sXL[4][4][32][8];   // [warp][stage][lane][ch]
    __shared__ __align__(16) float sEA[4][4][8];       // [warp][stage][ch]
    int tid = threadIdx.x;
    int warp = tid >> 5, lane = tid & 31;
    int gw = blockIdx.x * 4 + warp;
    if (gw >= NN) return;                // warp-private; no block syncs below
    int n = gw;
    int hc = lane * 8;

    ull we2[8][4];
#pragma unroll
    for (int k = 0; k < 8; ++k) {
        ulonglong2 u0 = *reinterpret_cast<const ulonglong2*>(&We[k * HC + hc]);
        ulonglong2 u1 = *reinterpret_cast<const ulonglong2*>(&We[k * HC + hc + 4]);
        we2[k][0] = u0.x; we2[k][1] = u0.y; we2[k][2] = u1.x; we2[k][3] = u1.y;
    }
    const ull c06 = dup2(0.6f), c04 = dup2(0.4f);
    ull att06[4], att04[4];
    {
        ulonglong2 a0 = *reinterpret_cast<const ulonglong2*>(&att[hc]);
        ulonglong2 a1 = *reinterpret_cast<const ulonglong2*>(&att[hc + 4]);
        ull a2[4] = {a0.x, a0.y, a1.x, a1.y};
#pragma unroll
        for (int q = 0; q < 4; ++q) {
            att06[q] = mul2(a2[q], c06);
            att04[q] = mul2(a2[q], c04);
        }
    }
    ull xr2[4];
    {
        ulonglong2 r0 = *reinterpret_cast<const ulonglong2*>(&g_xr[(size_t)n * HC + hc]);
        ulonglong2 r1 = *reinterpret_cast<const ulonglong2*>(&g_xr[(size_t)n * HC + hc + 4]);
        xr2[0] = r0.x; xr2[1] = r0.y; xr2[2] = r1.x; xr2[3] = r1.y;
    }

    int beg = g_rowptr[n], end = g_rowptr[n + 1];
    int last = end - 1;
    unsigned xlb = (unsigned)__cvta_generic_to_shared(&sXL[warp][0][lane][0]);
    unsigned eab = (unsigned)__cvta_generic_to_shared(&sEA[warp][0][0]);

    // issue prefetch of edge pp into stage st (1 cp.async group per lane)
    auto pref = [&](int pp, int st) {
        pp = min(pp, last);
        int eid = g_eid[pp];
        int s   = g_esrc[pp];
        const float* xs = &g_xl[(size_t)s * HC + hc];
        unsigned dst = xlb + (unsigned)(st * 32 * 8 * 4);
        cpa16(dst, xs, 16);
        cpa16(dst + 16, xs + 4, 16);
        if (lane < 2) {
            const float* pe = (eid < EE) ? (eattr + (size_t)eid * 8)
                                         : (g_sl + (size_t)(eid - EE) * 8);
            cpa16(eab + (unsigned)(st * 32 + lane * 16), pe + lane * 4, 16);
        }
        CP_COMMIT();
    };

#pragma unroll
    for (int st = 0; st < 4; ++st) pref(beg + st, st);

    float den = 0.f;
    ull acc2[4] = {0, 0, 0, 0};

    for (int p = beg; p < end; ++p) {
        int st = (p - beg) & 3;
        CP_WAIT3();
        __syncwarp();
        // read this lane's 8 channels of xl + broadcast edge attrs
        const float* xsm = &sXL[warp][st][lane][0];
        ulonglong2 xa = *reinterpret_cast<const ulonglong2*>(xsm);
        ulonglong2 xb = *reinterpret_cast<const ulonglong2*>(xsm + 4);
        ull xl2[4] = {xa.x, xa.y, xb.x, xb.y};
        float ea[8];
        {
            float4 e0 = *reinterpret_cast<const float4*>(&sEA[warp][st][0]);
            float4 e1 = *reinterpret_cast<const float4*>(&sEA[warp][st][4]);
            ea[0] = e0.x; ea[1] = e0.y; ea[2] = e0.z; ea[3] = e0.w;
            ea[4] = e1.x; ea[5] = e1.y; ea[6] = e1.z; ea[7] = e1.w;
        }
        __syncwarp();
        pref(p + 4, st);

        ull m2v[4];
#pragma unroll
        for (int q = 0; q < 4; ++q) m2v[q] = add2(xl2[q], xr2[q]);
#pragma unroll
        for (int k = 0; k < 8; ++k) {
            ull ek = dup2(ea[k]);
#pragma unroll
            for (int q = 0; q < 4; ++q) m2v[q] = fma2(ek, we2[k][q], m2v[q]);
        }
        ull sc2 = 0;
#pragma unroll
        for (int q = 0; q < 4; ++q)
            sc2 = fma2(att04[q], abs2(m2v[q]), fma2(att06[q], m2v[q], sc2));
        float slo, shi;
        unpack2(sc2, slo, shi);
        float sc = slo + shi;
        sc += __shfl_xor_sync(0xffffffffu, sc, 1);
        sc += __shfl_xor_sync(0xffffffffu, sc, 2);

        float ex = __expf(sc);
        den += ex;
        ull exp2 = dup2(ex);
#pragma unroll
        for (int q = 0; q < 4; ++q) acc2[q] = fma2(exp2, xl2[q], acc2[q]);
    }

    float inv = 1.f / den;
    float4 b0 = *reinterpret_cast<const float4*>(&bias[hc]);
    float4 b1 = *reinterpret_cast<const float4*>(&bias[hc + 4]);
    float bb[8] = {b0.x, b0.y, b0.z, b0.w, b1.x, b1.y, b1.z, b1.w};
    __nv_bfloat16 oh[8], ol[8];
#pragma unroll
    for (int q = 0; q < 4; ++q) {
        float alo, ahi;
        unpack2(acc2[q], alo, ahi);
        float v0 = fmaf(alo, inv, bb[2 * q]);
        float v1 = fmaf(ahi, inv, bb[2 * q + 1]);
        v0 = (v0 > 0.f) ? v0 : 0.2f * v0;
        v1 = (v1 > 0.f) ? v1 : 0.2f * v1;
        splitf(v0, oh[2 * q], ol[2 * q]);
        splitf(v1, oh[2 * q + 1], ol[2 * q + 1]);
    }
    uint4 ph, pl;
    {
        unsigned uh[4], ul[4];
#pragma unroll
        for (int q = 0; q < 4; ++q) {
            __nv_bfloat162 th = __halves2bfloat162(oh[2 * q], oh[2 * q + 1]);
            __nv_bfloat162 tl = __halves2bfloat162(ol[2 * q], ol[2 * q + 1]);
            uh[q] = *reinterpret_cast<unsigned*>(&th);
            ul[q] = *reinterpret_cast<unsigned*>(&tl);
        }
        ph = make_uint4(uh[0], uh[1], uh[2], uh[3]);
        pl = make_uint4(ul[0], ul[1], ul[2], ul[3]);
    }
    *reinterpret_cast<uint4*>(&g_ah[(size_t)n * HC + hc]) = ph;
    *reinterpret_cast<uint4*>(&g_al[(size_t)n * HC + hc]) = pl;
}

// ---------------- fused MLP head (warp per node) ----------------
__global__ void __launch_bounds__(256) k_mlp(
    const float* __restrict__ W0, const float* __restrict__ b0,
    const float* __restrict__ W1, const float* __restrict__ b1,
    const float* __restrict__ W2, const float* __restrict__ b2,
    const float* __restrict__ W3, const float* __restrict__ b3,
    float* __restrict__ out) {
    __shared__ float sW0[16 * 256];
    __shared__ float sW1[256], sW2[256], sW3[64];
    __shared__ float sb[52];
    int tid = threadIdx.x;
    {
        int k = tid;
#pragma unroll
        for (int j = 0; j < 16; ++j) sW0[j * 256 + k] = W0[k * 16 + j];
    }
    if (tid < 256) { sW1[tid] = W1[tid]; sW2[tid] = W2[tid]; }
    if (tid < 64)  sW3[tid] = W3[tid];
    if (tid < 16)  { sb[tid] = b0[tid]; sb[16 + tid] = b1[tid]; sb[32 + tid] = b2[tid]; }
    if (tid < 4)   sb[48 + tid] = b3[tid];
    __syncthreads();

    int gw = (blockIdx.x * blockDim.x + tid) >> 5;
    int lane = tid & 31;
    if (gw >= NN) return;
    int n = gw;

    float hin[8];
    {
        uint4 uh = *reinterpret_cast<const uint4*>(&g_ah[(size_t)n * HC + lane * 8]);
        uint4 ul = *reinterpret_cast<const uint4*>(&g_al[(size_t)n * HC + lane * 8]);
        unsigned ah[4] = {uh.x, uh.y, uh.z, uh.w};
        unsigned al[4] = {ul.x, ul.y, ul.z, ul.w};
#pragma unroll
        for (int q = 0; q < 4; ++q) {
            float2 fh = __bfloat1622float2(*reinterpret_cast<__nv_bfloat162*>(&ah[q]));
            float2 fl = __bfloat1622float2(*reinterpret_cast<__nv_bfloat162*>(&al[q]));
            hin[2 * q]     = fh.x + fl.x;
            hin[2 * q + 1] = fh.y + fl.y;
        }
    }
    float v[16];
#pragma unroll
    for (int j = 0; j < 16; ++j) {
        float4 w0 = *reinterpret_cast<float4*>(&sW0[j * 256 + lane * 8]);
        float4 w1 = *reinterpret_cast<float4*>(&sW0[j * 256 + lane * 8 + 4]);
        float p = hin[0] * w0.x;
        p = fmaf(hin[1], w0.y, p); p = fmaf(hin[2], w0.z, p); p = fmaf(hin[3], w0.w, p);
        p = fmaf(hin[4], w1.x, p); p = fmaf(hin[5], w1.y, p);
        p = fmaf(hin[6], w1.z, p); p = fmaf(hin[7], w1.w, p);
        v[j] = p;
    }
#pragma unroll
    for (int j = 0; j < 16; ++j) {
#pragma unroll
        for (int d = 16; d > 0; d >>= 1) v[j] += __shfl_xor_sync(0xffffffffu, v[j], d);
        v[j] = fmaxf(v[j] + sb[j], 0.f);
    }
    float u[16];
#pragma unroll
    for (int j = 0; j < 16; ++j) {
        float p = sb[16 + j];
#pragma unroll
        for (int k = 0; k < 16; ++k) p = fmaf(v[k], sW1[k * 16 + j], p);
        u[j] = fmaxf(p, 0.f);
    }
#pragma unroll
    for (int j = 0; j < 16; ++j) {
        float p = sb[32 + j];
#pragma unroll
        for (int k = 0; k < 16; ++k) p = fmaf(u[k], sW2[k * 16 + j], p);
        v[j] = fmaxf(p, 0.f);
    }
    if (lane < 4) {
        float p = sb[48 + lane];
#pragma unroll
        for (int k = 0; k < 16; ++k) p = fmaf(v[k], sW3[k * 4 + lane], p);
        out[n * 4 + lane] = p;
    }
}

// ---------------- launch ----------------
extern "C" void kernel_launch(void* const* d_in, const int* in_sizes, int n_in,
                              void* d_out, int out_size) {
    const float* x     = (const float*)d_in[0];
    const int*   ei    = (const int*)d_in[1];
    const float* eattr = (const float*)d_in[2];
    const float* P[29];
    for (int i = 0; i < 29; ++i) P[i] = (const float*)d_in[3 + i];
    const int* src = ei;
    const int* dst = ei + EE;
    float* out = (float*)d_out;

    cudaFuncSetAttribute(k_gemm_mma, cudaFuncAttributeMaxDynamicSharedMemorySize, SMEM_MMA);

    // weight split (layers 1-2: Wl1, Wr1, Wl2, Wr2)
    dim3 gsw(HC * HC / 256, 1, 4);
    k_splitw<<<gsw, 256>>>(P[7], P[9], P[14], P[16]);

    // CSR
    k_zero_init<<<(NN + 255) / 256, 256>>>();
    k_count<<<(EE + 255) / 256, 256>>>(dst);
    k_scan<<<1, 1024>>>();
    k_scatter<<<(ET + 255) / 256, 256>>>(src, dst);
    k_slmean<<<(NN * 32 + 255) / 256, 256>>>(eattr);

    dim3 gg((NN + BM - 1) / BM, HC / BN, 2);
    dim3 gm((NN + GBM - 1) / GBM, HC / GBN, 2);

    // layer 0 (K=16, input = x)
    k_gemm<<<gg, 256>>>(x, P[0], P[1], P[2], P[3]);
    k_attn<<<(NN * 32 + 127) / 128, 128>>>(eattr, P[4], P[5], P[6]);
    // layer 1 (K=256)
    k_gemm_mma<<<gm, 256, SMEM_MMA>>>(0, P[8], P[10]);
    k_attn<<<(NN * 32 + 127) / 128, 128>>>(eattr, P[11], P[12], P[13]);
    // layer 2
    k_gemm_mma<<<gm, 256, SMEM_MMA>>>(2, P[15], P[17]);
    k_attn<<<(NN * 32 + 127) / 128, 128>>>(eattr, P[18], P[19], P[20]);

    // MLP head
    k_mlp<<<(NN * 32 + 255) / 256, 256>>>(P[21], P[22], P[23], P[24],
                                          P[25], P[26], P[27], P[28], out);
}

// round 15
// speedup vs baseline: 1.0771x; 1.0771x over previous
#include <cuda_runtime.h>
#include <cuda_bf16.h>
#include <math_constants.h>

#define NN 20000
#define EE 320000
#define ET (EE + NN)
#define HC 256

// ---------------- scratch (device globals; no allocation) ----------------
__device__ float g_xl[(size_t)NN * HC];         // source transform (fp32)
__device__ float g_xr[(size_t)NN * HC];         // dest transform   (fp32)
__device__ __nv_bfloat16 g_ah[(size_t)NN * HC]; // node features hi
__device__ __nv_bfloat16 g_al[(size_t)NN * HC]; // node features lo
__device__ __nv_bfloat16 g_wh[4][HC * HC];      // transposed weight hi  [n][k]
__device__ __nv_bfloat16 g_wl[4][HC * HC];      // transposed weight lo  [n][k]
__device__ int   g_deg[NN];
__device__ int   g_fill[NN];
__device__ int   g_rowptr[NN + 1];
__device__ int   g_eid[ET];
__device__ int   g_esrc[ET];

typedef unsigned long long ull;

__device__ __forceinline__ void splitf(float v, __nv_bfloat16& h, __nv_bfloat16& l) {
    h = __float2bfloat16(v);
    l = __float2bfloat16(v - __bfloat162float(h));
}

// ---- f32x2 packed helpers ----
__device__ __forceinline__ ull dup2(float s) {
    ull r; asm("mov.b64 %0, {%1, %1};" : "=l"(r) : "f"(s)); return r;
}
__device__ __forceinline__ ull fma2(ull a, ull b, ull c) {
    ull r; asm("fma.rn.f32x2 %0, %1, %2, %3;" : "=l"(r) : "l"(a), "l"(b), "l"(c)); return r;
}
__device__ __forceinline__ ull mul2(ull a, ull b) {
    ull r; asm("mul.rn.f32x2 %0, %1, %2;" : "=l"(r) : "l"(a), "l"(b)); return r;
}
__device__ __forceinline__ ull add2(ull a, ull b) {
    ull r; asm("add.rn.f32x2 %0, %1, %2;" : "=l"(r) : "l"(a), "l"(b)); return r;
}
__device__ __forceinline__ ull abs2(ull a) {
    ull r; asm("and.b64 %0, %1, 0x7FFFFFFF7FFFFFFF;" : "=l"(r) : "l"(a)); return r;
}
__device__ __forceinline__ void unpack2(ull v, float& lo, float& hi) {
    asm("mov.b64 {%0, %1}, %2;" : "=f"(lo), "=f"(hi) : "l"(v));
}

// ---- ldmatrix / cp.async ----
__device__ __forceinline__ void ldsm4(unsigned& r0, unsigned& r1, unsigned& r2, unsigned& r3,
                                      unsigned addr) {
    asm volatile("ldmatrix.sync.aligned.m8n8.x4.shared.b16 {%0,%1,%2,%3}, [%4];"
                 : "=r"(r0), "=r"(r1), "=r"(r2), "=r"(r3) : "r"(addr));
}
__device__ __forceinline__ void cpa16(unsigned sa, const void* ga, int srcbytes) {
    asm volatile("cp.async.ca.shared.global [%0], [%1], 16, %2;"
                 :: "r"(sa), "l"(ga), "r"(srcbytes));
}
#define CP_COMMIT() asm volatile("cp.async.commit_group;")
#define CP_WAIT0()  asm volatile("cp.async.wait_group 0;")

// ---------------- weight split + transpose (+ counter zeroing) ----------------
__global__ void k_splitw(const float* __restrict__ Wa, const float* __restrict__ Wb,
                         const float* __restrict__ Wc, const float* __restrict__ Wd) {
    const float* W = (blockIdx.z == 0) ? Wa : (blockIdx.z == 1) ? Wb
                   : (blockIdx.z == 2) ? Wc : Wd;
    int idx = blockIdx.x * blockDim.x + threadIdx.x;
    int k = idx >> 8, n = idx & 255;
    float v = W[idx];
    __nv_bfloat16 h, l;
    splitf(v, h, l);
    g_wh[blockIdx.z][n * HC + k] = h;
    g_wl[blockIdx.z][n * HC + k] = l;
    if (blockIdx.z == 0 && idx < NN) { g_deg[idx] = 0; g_fill[idx] = 0; }
}

// ---------------- CSR build ----------------
__global__ void k_count(const int* __restrict__ dst) {
    int e = blockIdx.x * blockDim.x + threadIdx.x;
    if (e < EE) atomicAdd(&g_deg[dst[e]], 1);
}

#define NCHUNK 20
__global__ void __launch_bounds__(1024) k_scan() {
    __shared__ int wsum[32];
    __shared__ int woff[32];
    __shared__ int s_carry;
    int tid = threadIdx.x, lane = tid & 31, wid = tid >> 5;
    int v[NCHUNK];
#pragma unroll
    for (int j = 0; j < NCHUNK; ++j) {
        int i = j * 1024 + tid;
        v[j] = (i < NN) ? (g_deg[i] + 1) : 0;
    }
    if (tid == 0) { g_rowptr[0] = 0; s_carry = 0; }
    __syncthreads();
#pragma unroll
    for (int j = 0; j < NCHUNK; ++j) {
        int x = v[j];
#pragma unroll
        for (int off = 1; off < 32; off <<= 1) {
            int t = __shfl_up_sync(0xffffffffu, x, off);
            if (lane >= off) x += t;
        }
        if (lane == 31) wsum[wid] = x;
        __syncthreads();
        if (wid == 0) {
            int s = wsum[lane];
            int y = s;
#pragma unroll
            for (int off = 1; off < 32; off <<= 1) {
                int t = __shfl_up_sync(0xffffffffu, y, off);
                if (lane >= off) y += t;
            }
            woff[lane] = y - s;
        }
        __syncthreads();
        int incl = x + woff[wid] + s_carry;
        int i = j * 1024 + tid;
        if (i < NN) g_rowptr[i + 1] = incl;
        __syncthreads();
        if (tid == 1023) s_carry = incl;
        __syncthreads();
    }
}

// scatter: real edges fill [rowptr[d], rowptr[d]+deg); self-loop pinned at rowptr[d+1]-1
__global__ void k_scatter(const int* __restrict__ src, const int* __restrict__ dst) {
    int e = blockIdx.x * blockDim.x + threadIdx.x;
    if (e >= ET) return;
    int s, pos;
    if (e < EE) {
        s = src[e];
        int d = dst[e];
        pos = g_rowptr[d] + atomicAdd(&g_fill[d], 1);
    } else {
        s = e - EE;
        pos = g_rowptr[s + 1] - 1;
    }
    g_eid[pos]  = e;
    g_esrc[pos] = s;
}

// ---------------- fp32 GEMM (layer 0 only, K=16), xl+xr fused via z ----------------
#define BM 128
#define BN 128
#define BK 16
__global__ void __launch_bounds__(256) k_gemm(
    const float* __restrict__ A,
    const float* __restrict__ W0, const float* __restrict__ b0,
    const float* __restrict__ W1, const float* __restrict__ b1) {
    __shared__ float As[BK][BM + 4];
    __shared__ float Bs[BK][BN];
    const float* W    = blockIdx.z ? W1 : W0;
    const float* bias = blockIdx.z ? b1 : b0;
    float* O          = blockIdx.z ? g_xr : g_xl;
    const int K = 16;
    int tid = threadIdx.x;
    int tx = tid & 15, ty = tid >> 4;
    int row0 = blockIdx.x * BM;
    int col0 = blockIdx.y * BN;
    float acc[8][8];
#pragma unroll
    for (int i = 0; i < 8; ++i)
#pragma unroll
        for (int j = 0; j < 8; ++j) acc[i][j] = 0.f;

#pragma unroll
    for (int i = 0; i < 2; ++i) {
        int f = tid * 2 + i;
        int r = f >> 2, c4 = (f & 3) * 4;
        int gr = row0 + r;
        float4 v = make_float4(0.f, 0.f, 0.f, 0.f);
        if (gr < NN) v = *reinterpret_cast<const float4*>(&A[(size_t)gr * K + c4]);
        As[c4 + 0][r] = v.x; As[c4 + 1][r] = v.y;
        As[c4 + 2][r] = v.z; As[c4 + 3][r] = v.w;
    }
#pragma unroll
    for (int i = 0; i < 2; ++i) {
        int f = tid * 2 + i;
        int r = f >> 5, c4 = (f & 31) * 4;
        *reinterpret_cast<float4*>(&Bs[r][c4]) =
            *reinterpret_cast<const float4*>(&W[(size_t)r * HC + col0 + c4]);
    }
    __syncthreads();
#pragma unroll
    for (int kk = 0; kk < BK; ++kk) {
        float a[8], b[8];
        *reinterpret_cast<float4*>(&a[0]) = *reinterpret_cast<float4*>(&As[kk][ty * 8]);
        *reinterpret_cast<float4*>(&a[4]) = *reinterpret_cast<float4*>(&As[kk][ty * 8 + 4]);
        *reinterpret_cast<float4*>(&b[0]) = *reinterpret_cast<float4*>(&Bs[kk][tx * 8]);
        *reinterpret_cast<float4*>(&b[4]) = *reinterpret_cast<float4*>(&Bs[kk][tx * 8 + 4]);
#pragma unroll
        for (int i = 0; i < 8; ++i)
#pragma unroll
            for (int j = 0; j < 8; ++j)
                acc[i][j] = fmaf(a[i], b[j], acc[i][j]);
    }
#pragma unroll
    for (int i = 0; i < 8; ++i) {
        int gr = row0 + ty * 8 + i;
        if (gr >= NN) continue;
#pragma unroll
        for (int j4 = 0; j4 < 2; ++j4) {
            int c = col0 + tx * 8 + j4 * 4;
            float4 o;
            o.x = acc[i][j4 * 4 + 0] + bias[c + 0];
            o.y = acc[i][j4 * 4 + 1] + bias[c + 1];
            o.z = acc[i][j4 * 4 + 2] + bias[c + 2];
            o.w = acc[i][j4 * 4 + 3] + bias[c + 3];
            *reinterpret_cast<float4*>(&O[(size_t)gr * HC + c]) = o;
        }
    }
}

// ---------------- split-bf16 tensor-core GEMM, cp.async double-buffered ----------------
#define GBM 64
#define GBN 128
#define GKB 32
#define AST 40
#define NIT (HC / GKB)
#define SZ_A (2 * GBM * AST)
#define SZ_B (2 * GBN * AST)
#define SMEM_MMA ((2 * SZ_A + 2 * SZ_B) * 2)

__device__ __forceinline__ void mma16816(float* c, const unsigned* a, const unsigned* b) {
    asm volatile(
        "mma.sync.aligned.m16n8k16.row.col.f32.bf16.bf16.f32 "
        "{%0,%1,%2,%3}, {%4,%5,%6,%7}, {%8,%9}, {%0,%1,%2,%3};\n"
        : "+f"(c[0]), "+f"(c[1]), "+f"(c[2]), "+f"(c[3])
        : "r"(a[0]), "r"(a[1]), "r"(a[2]), "r"(a[3]), "r"(b[0]), "r"(b[1]));
}

__global__ void __launch_bounds__(256) k_gemm_mma(
    int matbase,
    const float* __restrict__ b0, const float* __restrict__ b1) {
    extern __shared__ __nv_bfloat16 dyn[];
    int mat = matbase + blockIdx.z;
    const float* bias = blockIdx.z ? b1 : b0;
    float* O          = blockIdx.z ? g_xr : g_xl;
    const __nv_bfloat16* Wh = g_wh[mat];
    const __nv_bfloat16* Wl = g_wl[mat];

    unsigned base   = (unsigned)__cvta_generic_to_shared(dyn);
    unsigned addrAh = base;
    unsigned addrAl = addrAh + SZ_A * 2;
    unsigned addrBh = addrAl + SZ_A * 2;
    unsigned addrBl = addrBh + SZ_B * 2;

    int tid = threadIdx.x;
    int warp = tid >> 5, lane = tid & 31;
    int wm = (warp >> 2) * 32;
    int wn = (warp & 3) * 32;
    int row0 = blockIdx.x * GBM;
    int col0 = blockIdx.y * GBN;
    int group = lane >> 2, tg = lane & 3;

    int st_m  = tid >> 2, st_c8 = (tid & 3) * 8;
    int st_gr = row0 + st_m;
    int st_grc = st_gr < NN ? st_gr : 0;
    int st_sb  = (st_gr < NN) ? 16 : 0;

    int a_row = lane & 15;
    int a_k   = (lane >> 4) * 8;
    int b_n   = (lane & 7) + ((lane >> 4) & 1) * 8;
    int b_k   = ((lane >> 3) & 1) * 8;

    float acc[2][4][4];
#pragma unroll
    for (int mt = 0; mt < 2; ++mt)
#pragma unroll
        for (int nt = 0; nt < 4; ++nt)
#pragma unroll
            for (int q = 0; q < 4; ++q) acc[mt][nt][q] = 0.f;

    auto stage = [&](int k0, int buf) {
        unsigned da = (unsigned)(((buf * GBM + st_m) * AST + st_c8) * 2);
        cpa16(addrAh + da, &g_ah[(size_t)st_grc * HC + k0 + st_c8], st_sb);
        cpa16(addrAl + da, &g_al[(size_t)st_grc * HC + k0 + st_c8], st_sb);
#pragma unroll
        for (int t = 0; t < 2; ++t) {
            int idx = tid + t * 256;
            int n = idx >> 2, c8 = (idx & 3) * 8;
            size_t off = (size_t)(col0 + n) * HC + k0 + c8;
            unsigned db = (unsigned)(((buf * GBN + n) * AST + c8) * 2);
            cpa16(addrBh + db, &Wh[off], 16);
            cpa16(addrBl + db, &Wl[off], 16);
        }
        CP_COMMIT();
    };

    stage(0, 0);
    int cur = 0;
    for (int it = 0; it < NIT; ++it) {
        CP_WAIT0();
        __syncthreads();
        if (it + 1 < NIT) stage((it + 1) * GKB, cur ^ 1);
#pragma unroll
        for (int kk = 0; kk < GKB; kk += 16) {
            unsigned ah[2][4], al[2][4];
#pragma unroll
            for (int mt = 0; mt < 2; ++mt) {
                unsigned offA = (unsigned)((((cur * GBM) + wm + mt * 16 + a_row) * AST + kk + a_k) * 2);
                ldsm4(ah[mt][0], ah[mt][1], ah[mt][2], ah[mt][3], addrAh + offA);
                ldsm4(al[mt][0], al[mt][1], al[mt][2], al[mt][3], addrAl + offA);
            }
            unsigned bh[4][2], bl[4][2];
#pragma unroll
            for (int pr = 0; pr < 2; ++pr) {
                unsigned offB = (unsigned)((((cur * GBN) + wn + pr * 16 + b_n) * AST + kk + b_k) * 2);
                ldsm4(bh[2 * pr][0], bh[2 * pr][1], bh[2 * pr + 1][0], bh[2 * pr + 1][1],
                      addrBh + offB);
                ldsm4(bl[2 * pr][0], bl[2 * pr][1], bl[2 * pr + 1][0], bl[2 * pr + 1][1],
                      addrBl + offB);
            }
#pragma unroll
            for (int mt = 0; mt < 2; ++mt)
#pragma unroll
                for (int nt = 0; nt < 4; ++nt) {
                    mma16816(acc[mt][nt], ah[mt], bh[nt]);
                    mma16816(acc[mt][nt], ah[mt], bl[nt]);
                    mma16816(acc[mt][nt], al[mt], bh[nt]);
                }
        }
        __syncthreads();
        cur ^= 1;
    }
#pragma unroll
    for (int mt = 0; mt < 2; ++mt) {
#pragma unroll
        for (int nt = 0; nt < 4; ++nt) {
            int n = col0 + wn + nt * 8 + tg * 2;
            float2 bb = *reinterpret_cast<const float2*>(&bias[n]);
            int m = row0 + wm + mt * 16 + group;
            if (m < NN) {
                float2 o = make_float2(acc[mt][nt][0] + bb.x, acc[mt][nt][1] + bb.y);
                *reinterpret_cast<float2*>(&O[(size_t)m * HC + n]) = o;
            }
            int m2 = m + 8;
            if (m2 < NN) {
                float2 o = make_float2(acc[mt][nt][2] + bb.x, acc[mt][nt][3] + bb.y);
                *reinterpret_cast<float2*>(&O[(size_t)m2 * HC + n]) = o;
            }
        }
    }
}

// ---------------- fused GATv2 attention (R6 loop; in-warp self-loop mean) ----------------
__device__ __forceinline__ void attn_ld(const float* __restrict__ eattr,
                                        int eid, int s, int hc,
                                        ull* xl2, float* ea) {
    const float* pe = eattr + (size_t)eid * 8;      // real edges only
    float4 e0 = *reinterpret_cast<const float4*>(pe);
    float4 e1 = *reinterpret_cast<const float4*>(pe + 4);
    ea[0] = e0.x; ea[1] = e0.y; ea[2] = e0.z; ea[3] = e0.w;
    ea[4] = e1.x; ea[5] = e1.y; ea[6] = e1.z; ea[7] = e1.w;
    ulonglong2 xa = *reinterpret_cast<const ulonglong2*>(&g_xl[(size_t)s * HC + hc]);
    ulonglong2 xb = *reinterpret_cast<const ulonglong2*>(&g_xl[(size_t)s * HC + hc + 4]);
    xl2[0] = xa.x; xl2[1] = xa.y; xl2[2] = xb.x; xl2[3] = xb.y;
}

__global__ void __launch_bounds__(128) k_attn(
    const float* __restrict__ eattr,
    const float* __restrict__ We, const float* __restrict__ att,
    const float* __restrict__ bias) {
    int gw = (blockIdx.x * blockDim.x + threadIdx.x) >> 5;
    int lane = threadIdx.x & 31;
    if (gw >= NN) return;
    int n = gw;
    int hc = lane * 8;

    ull we2[8][4];
#pragma unroll
    for (int k = 0; k < 8; ++k) {
        ulonglong2 u0 = *reinterpret_cast<const ulonglong2*>(&We[k * HC + hc]);
        ulonglong2 u1 = *reinterpret_cast<const ulonglong2*>(&We[k * HC + hc + 4]);
        we2[k][0] = u0.x; we2[k][1] = u0.y; we2[k][2] = u1.x; we2[k][3] = u1.y;
    }
    const ull c06 = dup2(0.6f), c04 = dup2(0.4f);
    ull att06[4], att04[4];
    {
        ulonglong2 a0 = *reinterpret_cast<const ulonglong2*>(&att[hc]);
        ulonglong2 a1 = *reinterpret_cast<const ulonglong2*>(&att[hc + 4]);
        ull a2[4] = {a0.x, a0.y, a1.x, a1.y};
#pragma unroll
        for (int q = 0; q < 4; ++q) {
            att06[q] = mul2(a2[q], c06);
            att04[q] = mul2(a2[q], c04);
        }
    }
    ull xr2[4];
    {
        ulonglong2 r0 = *reinterpret_cast<const ulonglong2*>(&g_xr[(size_t)n * HC + hc]);
        ulonglong2 r1 = *reinterpret_cast<const ulonglong2*>(&g_xr[(size_t)n * HC + hc + 4]);
        xr2[0] = r0.x; xr2[1] = r0.y; xr2[2] = r1.x; xr2[3] = r1.y;
    }
    // self xl (used for the self-loop edge, processed last)
    ull xls[4];
    {
        ulonglong2 s0 = *reinterpret_cast<const ulonglong2*>(&g_xl[(size_t)n * HC + hc]);
        ulonglong2 s1 = *reinterpret_cast<const ulonglong2*>(&g_xl[(size_t)n * HC + hc + 4]);
        xls[0] = s0.x; xls[1] = s0.y; xls[2] = s1.x; xls[3] = s1.y;
    }

    int beg = g_rowptr[n], end = g_rowptr[n + 1];
    int cnt = end - 1 - beg;          // real incoming edges (self-loop is at end-1)

    float den = 0.f;
    ull acc2[4] = {0, 0, 0, 0};
    float eas[8] = {0.f, 0.f, 0.f, 0.f, 0.f, 0.f, 0.f, 0.f};

    if (cnt > 0) {
        int lastp = beg + cnt - 1;
        int eidA = g_eid[beg], sA = g_esrc[beg];
        int p1 = min(beg + 1, lastp);
        int eidB = g_eid[p1], sB = g_esrc[p1];
        ull xlC[4]; float eaC[8];
        attn_ld(eattr, eidA, sA, hc, xlC, eaC);

        for (int p = beg; p <= lastp; ++p) {
            int p2 = min(p + 2, lastp);
            int eidN2 = g_eid[p2], sN2 = g_esrc[p2];
            ull xlN[4]; float eaN[8];
            attn_ld(eattr, eidB, sB, hc, xlN, eaN);

            ull m2v[4];
#pragma unroll
            for (int q = 0; q < 4; ++q) m2v[q] = add2(xlC[q], xr2[q]);
#pragma unroll
            for (int k = 0; k < 8; ++k) {
                ull ek = dup2(eaC[k]);
#pragma unroll
                for (int q = 0; q < 4; ++q) m2v[q] = fma2(ek, we2[k][q], m2v[q]);
            }
            ull sc2 = 0;
#pragma unroll
            for (int q = 0; q < 4; ++q)
                sc2 = fma2(att04[q], abs2(m2v[q]), fma2(att06[q], m2v[q], sc2));
            float slo, shi;
            unpack2(sc2, slo, shi);
            float sc = slo + shi;
            sc += __shfl_xor_sync(0xffffffffu, sc, 1);
            sc += __shfl_xor_sync(0xffffffffu, sc, 2);

            float ex = __expf(sc);
            den += ex;
            ull exp2 = dup2(ex);
#pragma unroll
            for (int q = 0; q < 4; ++q) acc2[q] = fma2(exp2, xlC[q], acc2[q]);
#pragma unroll
            for (int k = 0; k < 8; ++k) eas[k] += eaC[k];

#pragma unroll
            for (int q = 0; q < 4; ++q) xlC[q] = xlN[q];
#pragma unroll
            for (int k = 0; k < 8; ++k) eaC[k] = eaN[k];
            eidB = eidN2; sB = sN2;
        }
    }

    // self-loop edge: ea = mean of incoming real edge attrs, xl = xl[n]
    {
        float minv = 1.f / (float)(cnt > 1 ? cnt : 1);
        ull m2v[4];
#pragma unroll
        for (int q = 0; q < 4; ++q) m2v[q] = add2(xls[q], xr2[q]);
#pragma unroll
        for (int k = 0; k < 8; ++k) {
            ull ek = dup2(eas[k] * minv);
#pragma unroll
            for (int q = 0; q < 4; ++q) m2v[q] = fma2(ek, we2[k][q], m2v[q]);
        }
        ull sc2 = 0;
#pragma unroll
        for (int q = 0; q < 4; ++q)
            sc2 = fma2(att04[q], abs2(m2v[q]), fma2(att06[q], m2v[q], sc2));
        float slo, shi;
        unpack2(sc2, slo, shi);
        float sc = slo + shi;
        sc += __shfl_xor_sync(0xffffffffu, sc, 1);
        sc += __shfl_xor_sync(0xffffffffu, sc, 2);
        float ex = __expf(sc);
        den += ex;
        ull exp2 = dup2(ex);
#pragma unroll
        for (int q = 0; q < 4; ++q) acc2[q] = fma2(exp2, xls[q], acc2[q]);
    }

    float inv = 1.f / den;
    float4 b0 = *reinterpret_cast<const float4*>(&bias[hc]);
    float4 b1 = *reinterpret_cast<const float4*>(&bias[hc + 4]);
    float bb[8] = {b0.x, b0.y, b0.z, b0.w, b1.x, b1.y, b1.z, b1.w};
    __nv_bfloat16 oh[8], ol[8];
#pragma unroll
    for (int q = 0; q < 4; ++q) {
        float alo, ahi;
        unpack2(acc2[q], alo, ahi);
        float v0 = fmaf(alo, inv, bb[2 * q]);
        float v1 = fmaf(ahi, inv, bb[2 * q + 1]);
        v0 = (v0 > 0.f) ? v0 : 0.2f * v0;
        v1 = (v1 > 0.f) ? v1 : 0.2f * v1;
        splitf(v0, oh[2 * q], ol[2 * q]);
        splitf(v1, oh[2 * q + 1], ol[2 * q + 1]);
    }
    uint4 ph, pl;
    {
        unsigned uh[4], ul[4];
#pragma unroll
        for (int q = 0; q < 4; ++q) {
            __nv_bfloat162 th = __halves2bfloat162(oh[2 * q], oh[2 * q + 1]);
            __nv_bfloat162 tl = __halves2bfloat162(ol[2 * q], ol[2 * q + 1]);
            uh[q] = *reinterpret_cast<unsigned*>(&th);
            ul[q] = *reinterpret_cast<unsigned*>(&tl);
        }
        ph = make_uint4(uh[0], uh[1], uh[2], uh[3]);
        pl = make_uint4(ul[0], ul[1], ul[2], ul[3]);
    }
    *reinterpret_cast<uint4*>(&g_ah[(size_t)n * HC + hc]) = ph;
    *reinterpret_cast<uint4*>(&g_al[(size_t)n * HC + hc]) = pl;
}

// ---------------- fused MLP head (warp per node) ----------------
__global__ void __launch_bounds__(256) k_mlp(
    const float* __restrict__ W0, const float* __restrict__ b0,
    const float* __restrict__ W1, const float* __restrict__ b1,
    const float* __restrict__ W2, const float* __restrict__ b2,
    const float* __restrict__ W3, const float* __restrict__ b3,
    float* __restrict__ out) {
    __shared__ float sW0[16 * 256];
    __shared__ float sW1[256], sW2[256], sW3[64];
    __shared__ float sb[52];
    int tid = threadIdx.x;
    {
        int k = tid;
#pragma unroll
        for (int j = 0; j < 16; ++j) sW0[j * 256 + k] = W0[k * 16 + j];
    }
    if (tid < 256) { sW1[tid] = W1[tid]; sW2[tid] = W2[tid]; }
    if (tid < 64)  sW3[tid] = W3[tid];
    if (tid < 16)  { sb[tid] = b0[tid]; sb[16 + tid] = b1[tid]; sb[32 + tid] = b2[tid]; }
    if (tid < 4)   sb[48 + tid] = b3[tid];
    __syncthreads();

    int gw = (blockIdx.x * blockDim.x + tid) >> 5;
    int lane = tid & 31;
    if (gw >= NN) return;
    int n = gw;

    float hin[8];
    {
        uint4 uh = *reinterpret_cast<const uint4*>(&g_ah[(size_t)n * HC + lane * 8]);
        uint4 ul = *reinterpret_cast<const uint4*>(&g_al[(size_t)n * HC + lane * 8]);
        unsigned ah[4] = {uh.x, uh.y, uh.z, uh.w};
        unsigned al[4] = {ul.x, ul.y, ul.z, ul.w};
#pragma unroll
        for (int q = 0; q < 4; ++q) {
            float2 fh = __bfloat1622float2(*reinterpret_cast<__nv_bfloat162*>(&ah[q]));
            float2 fl = __bfloat1622float2(*reinterpret_cast<__nv_bfloat162*>(&al[q]));
            hin[2 * q]     = fh.x + fl.x;
            hin[2 * q + 1] = fh.y + fl.y;
        }
    }
    float v[16];
#pragma unroll
    for (int j = 0; j < 16; ++j) {
        float4 w0 = *reinterpret_cast<float4*>(&sW0[j * 256 + lane * 8]);
        float4 w1 = *reinterpret_cast<float4*>(&sW0[j * 256 + lane * 8 + 4]);
        float p = hin[0] * w0.x;
        p = fmaf(hin[1], w0.y, p); p = fmaf(hin[2], w0.z, p); p = fmaf(hin[3], w0.w, p);
        p = fmaf(hin[4], w1.x, p); p = fmaf(hin[5], w1.y, p);
        p = fmaf(hin[6], w1.z, p); p = fmaf(hin[7], w1.w, p);
        v[j] = p;
    }
#pragma unroll
    for (int j = 0; j < 16; ++j) {
#pragma unroll
        for (int d = 16; d > 0; d >>= 1) v[j] += __shfl_xor_sync(0xffffffffu, v[j], d);
        v[j] = fmaxf(v[j] + sb[j], 0.f);
    }
    float u[16];
#pragma unroll
    for (int j = 0; j < 16; ++j) {
        float p = sb[16 + j];
#pragma unroll
        for (int k = 0; k < 16; ++k) p = fmaf(v[k], sW1[k * 16 + j], p);
        u[j] = fmaxf(p, 0.f);
    }
#pragma unroll
    for (int j = 0; j < 16; ++j) {
        float p = sb[32 + j];
#pragma unroll
        for (int k = 0; k < 16; ++k) p = fmaf(u[k], sW2[k * 16 + j], p);
        v[j] = fmaxf(p, 0.f);
    }
    if (lane < 4) {
        float p = sb[48 + lane];
#pragma unroll
        for (int k = 0; k < 16; ++k) p = fmaf(v[k], sW3[k * 4 + lane], p);
        out[n * 4 + lane] = p;
    }
}

// ---------------- launch ----------------
extern "C" void kernel_launch(void* const* d_in, const int* in_sizes, int n_in,
                              void* d_out, int out_size) {
    const float* x     = (const float*)d_in[0];
    const int*   ei    = (const int*)d_in[1];
    const float* eattr = (const float*)d_in[2];
    const float* P[29];
    for (int i = 0; i < 29; ++i) P[i] = (const float*)d_in[3 + i];
    const int* src = ei;
    const int* dst = ei + EE;
    float* out = (float*)d_out;

    cudaFuncSetAttribute(k_gemm_mma, cudaFuncAttributeMaxDynamicSharedMemorySize, SMEM_MMA);

    // weight split (layers 1-2) + counter zeroing
    dim3 gsw(HC * HC / 256, 1, 4);
    k_splitw<<<gsw, 256>>>(P[7], P[9], P[14], P[16]);

    // CSR
    k_count<<<(EE + 255) / 256, 256>>>(dst);
    k_scan<<<1, 1024>>>();
    k_scatter<<<(ET + 255) / 256, 256>>>(src, dst);

    dim3 gg((NN + BM - 1) / BM, HC / BN, 2);
    dim3 gm((NN + GBM - 1) / GBM, HC / GBN, 2);

    // layer 0 (K=16, input = x)
    k_gemm<<<gg, 256>>>(x, P[0], P[1], P[2], P[3]);
    k_attn<<<(NN * 32 + 127) / 128, 128>>>(eattr, P[4], P[5], P[6]);
    // layer 1 (K=256)
    k_gemm_mma<<<gm, 256, SMEM_MMA>>>(0, P[8], P[10]);
    k_attn<<<(NN * 32 + 127) / 128, 128>>>(eattr, P[11], P[12], P[13]);
    // layer 2
    k_gemm_mma<<<gm, 256, SMEM_MMA>>>(2, P[15], P[17]);
    k_attn<<<(NN * 32 + 127) / 128, 128>>>(eattr, P[18], P[19], P[20]);

    // MLP head
    k_mlp<<<(NN * 32 + 255) / 256, 256>>>(P[21], P[22], P[23], P[24],
                                          P[25], P[26], P[27], P[28], out);
}

// round 16
// speedup vs baseline: 1.1521x; 1.0696x over previous
#include <cuda_runtime.h>
#include <cuda_bf16.h>
#include <math_constants.h>

#define NN 20000
#define EE 320000
#define ET (EE + NN)
#define HC 256

// ---------------- scratch (device globals; no allocation) ----------------
__device__ float g_sl[(size_t)NN * 8];          // self-loop edge attrs
__device__ float g_xl[(size_t)NN * HC];         // source transform (fp32)
__device__ float g_xr[(size_t)NN * HC];         // dest transform   (fp32)
__device__ __nv_bfloat16 g_ah[(size_t)NN * HC]; // node features hi
__device__ __nv_bfloat16 g_al[(size_t)NN * HC]; // node features lo
__device__ __nv_bfloat16 g_wh[4][HC * HC];      // transposed weight hi  [n][k]
__device__ __nv_bfloat16 g_wl[4][HC * HC];      // transposed weight lo  [n][k]
__device__ int   g_deg[NN];
__device__ int   g_fill[NN];
__device__ int   g_rowptr[NN + 1];
__device__ int   g_eid[ET];
__device__ int   g_esrc[ET];

typedef unsigned long long ull;

__device__ __forceinline__ void splitf(float v, __nv_bfloat16& h, __nv_bfloat16& l) {
    h = __float2bfloat16(v);
    l = __float2bfloat16(v - __bfloat162float(h));
}

// ---- f32x2 packed helpers ----
__device__ __forceinline__ ull dup2(float s) {
    ull r; asm("mov.b64 %0, {%1, %1};" : "=l"(r) : "f"(s)); return r;
}
__device__ __forceinline__ ull fma2(ull a, ull b, ull c) {
    ull r; asm("fma.rn.f32x2 %0, %1, %2, %3;" : "=l"(r) : "l"(a), "l"(b), "l"(c)); return r;
}
__device__ __forceinline__ ull mul2(ull a, ull b) {
    ull r; asm("mul.rn.f32x2 %0, %1, %2;" : "=l"(r) : "l"(a), "l"(b)); return r;
}
__device__ __forceinline__ ull add2(ull a, ull b) {
    ull r; asm("add.rn.f32x2 %0, %1, %2;" : "=l"(r) : "l"(a), "l"(b)); return r;
}
__device__ __forceinline__ ull abs2(ull a) {
    ull r; asm("and.b64 %0, %1, 0x7FFFFFFF7FFFFFFF;" : "=l"(r) : "l"(a)); return r;
}
__device__ __forceinline__ void unpack2(ull v, float& lo, float& hi) {
    asm("mov.b64 {%0, %1}, %2;" : "=f"(lo), "=f"(hi) : "l"(v));
}

// ---- ldmatrix / cp.async ----
__device__ __forceinline__ void ldsm4(unsigned& r0, unsigned& r1, unsigned& r2, unsigned& r3,
                                      unsigned addr) {
    asm volatile("ldmatrix.sync.aligned.m8n8.x4.shared.b16 {%0,%1,%2,%3}, [%4];"
                 : "=r"(r0), "=r"(r1), "=r"(r2), "=r"(r3) : "r"(addr));
}
__device__ __forceinline__ void cpa16(unsigned sa, const void* ga, int srcbytes) {
    asm volatile("cp.async.ca.shared.global [%0], [%1], 16, %2;"
                 :: "r"(sa), "l"(ga), "r"(srcbytes));
}
#define CP_COMMIT() asm volatile("cp.async.commit_group;")
#define CP_WAIT0()  asm volatile("cp.async.wait_group 0;")

// ---------------- weight split + transpose (+ counter zeroing) ----------------
__global__ void k_splitw(const float* __restrict__ Wa, const float* __restrict__ Wb,
                         const float* __restrict__ Wc, const float* __restrict__ Wd) {
    const float* W = (blockIdx.z == 0) ? Wa : (blockIdx.z == 1) ? Wb
                   : (blockIdx.z == 2) ? Wc : Wd;
    int idx = blockIdx.x * blockDim.x + threadIdx.x;
    int k = idx >> 8, n = idx & 255;
    float v = W[idx];
    __nv_bfloat16 h, l;
    splitf(v, h, l);
    g_wh[blockIdx.z][n * HC + k] = h;
    g_wl[blockIdx.z][n * HC + k] = l;
    if (blockIdx.z == 0 && idx < NN) { g_deg[idx] = 0; g_fill[idx] = 0; }
}

// ---------------- CSR build ----------------
__global__ void k_count(const int* __restrict__ dst) {
    int e = blockIdx.x * blockDim.x + threadIdx.x;
    if (e < EE) atomicAdd(&g_deg[dst[e]], 1);
}

#define NCHUNK 20
__global__ void __launch_bounds__(1024) k_scan() {
    __shared__ int wsum[32];
    __shared__ int woff[32];
    __shared__ int s_carry;
    int tid = threadIdx.x, lane = tid & 31, wid = tid >> 5;
    int v[NCHUNK];
#pragma unroll
    for (int j = 0; j < NCHUNK; ++j) {
        int i = j * 1024 + tid;
        v[j] = (i < NN) ? (g_deg[i] + 1) : 0;
    }
    if (tid == 0) { g_rowptr[0] = 0; s_carry = 0; }
    __syncthreads();
#pragma unroll
    for (int j = 0; j < NCHUNK; ++j) {
        int x = v[j];
#pragma unroll
        for (int off = 1; off < 32; off <<= 1) {
            int t = __shfl_up_sync(0xffffffffu, x, off);
            if (lane >= off) x += t;
        }
        if (lane == 31) wsum[wid] = x;
        __syncthreads();
        if (wid == 0) {
            int s = wsum[lane];
            int y = s;
#pragma unroll
            for (int off = 1; off < 32; off <<= 1) {
                int t = __shfl_up_sync(0xffffffffu, y, off);
                if (lane >= off) y += t;
            }
            woff[lane] = y - s;
        }
        __syncthreads();
        int incl = x + woff[wid] + s_carry;
        int i = j * 1024 + tid;
        if (i < NN) g_rowptr[i + 1] = incl;
        __syncthreads();
        if (tid == 1023) s_carry = incl;
        __syncthreads();
    }
}

__global__ void k_scatter(const int* __restrict__ src, const int* __restrict__ dst) {
    int e = blockIdx.x * blockDim.x + threadIdx.x;
    if (e >= ET) return;
    int s, d;
    if (e < EE) { s = src[e]; d = dst[e]; }
    else        { s = e - EE; d = s; }
    int pos = g_rowptr[d] + atomicAdd(&g_fill[d], 1);
    g_eid[pos]  = e;
    g_esrc[pos] = s;
}

// self-loop attr = mean of incoming edge attrs (warp per node, no atomics)
__global__ void __launch_bounds__(256) k_slmean(const float* __restrict__ eattr) {
    int gw = (blockIdx.x * blockDim.x + threadIdx.x) >> 5;
    int lane = threadIdx.x & 31;
    if (gw >= NN) return;
    int beg = g_rowptr[gw], end = g_rowptr[gw + 1];
    int slot = lane >> 3, ch = lane & 7;
    float v = 0.f;
    for (int p = beg + slot; p < end; p += 4) {
        int eid = g_eid[p];
        if (eid < EE) v += eattr[(size_t)eid * 8 + ch];
    }
    v += __shfl_xor_sync(0xffffffffu, v, 8);
    v += __shfl_xor_sync(0xffffffffu, v, 16);
    if (lane < 8) {
        int dg = end - beg - 1;
        float inv = 1.f / (float)(dg > 1 ? dg : 1);
        g_sl[(size_t)gw * 8 + lane] = v * inv;
    }
}

// ---------------- fp32 GEMM (layer 0 only, K=16), xl+xr fused via z ----------------
#define BM 128
#define BN 128
#define BK 16
__global__ void __launch_bounds__(256) k_gemm(
    const float* __restrict__ A,
    const float* __restrict__ W0, const float* __restrict__ b0,
    const float* __restrict__ W1, const float* __restrict__ b1) {
    __shared__ float As[BK][BM + 4];
    __shared__ float Bs[BK][BN];
    const float* W    = blockIdx.z ? W1 : W0;
    const float* bias = blockIdx.z ? b1 : b0;
    float* O          = blockIdx.z ? g_xr : g_xl;
    const int K = 16;
    int tid = threadIdx.x;
    int tx = tid & 15, ty = tid >> 4;
    int row0 = blockIdx.x * BM;
    int col0 = blockIdx.y * BN;
    float acc[8][8];
#pragma unroll
    for (int i = 0; i < 8; ++i)
#pragma unroll
        for (int j = 0; j < 8; ++j) acc[i][j] = 0.f;

#pragma unroll
    for (int i = 0; i < 2; ++i) {
        int f = tid * 2 + i;
        int r = f >> 2, c4 = (f & 3) * 4;
        int gr = row0 + r;
        float4 v = make_float4(0.f, 0.f, 0.f, 0.f);
        if (gr < NN) v = *reinterpret_cast<const float4*>(&A[(size_t)gr * K + c4]);
        As[c4 + 0][r] = v.x; As[c4 + 1][r] = v.y;
        As[c4 + 2][r] = v.z; As[c4 + 3][r] = v.w;
    }
#pragma unroll
    for (int i = 0; i < 2; ++i) {
        int f = tid * 2 + i;
        int r = f >> 5, c4 = (f & 31) * 4;
        *reinterpret_cast<float4*>(&Bs[r][c4]) =
            *reinterpret_cast<const float4*>(&W[(size_t)r * HC + col0 + c4]);
    }
    __syncthreads();
#pragma unroll
    for (int kk = 0; kk < BK; ++kk) {
        float a[8], b[8];
        *reinterpret_cast<float4*>(&a[0]) = *reinterpret_cast<float4*>(&As[kk][ty * 8]);
        *reinterpret_cast<float4*>(&a[4]) = *reinterpret_cast<float4*>(&As[kk][ty * 8 + 4]);
        *reinterpret_cast<float4*>(&b[0]) = *reinterpret_cast<float4*>(&Bs[kk][tx * 8]);
        *reinterpret_cast<float4*>(&b[4]) = *reinterpret_cast<float4*>(&Bs[kk][tx * 8 + 4]);
#pragma unroll
        for (int i = 0; i < 8; ++i)
#pragma unroll
            for (int j = 0; j < 8; ++j)
                acc[i][j] = fmaf(a[i], b[j], acc[i][j]);
    }
#pragma unroll
    for (int i = 0; i < 8; ++i) {
        int gr = row0 + ty * 8 + i;
        if (gr >= NN) continue;
#pragma unroll
        for (int j4 = 0; j4 < 2; ++j4) {
            int c = col0 + tx * 8 + j4 * 4;
            float4 o;
            o.x = acc[i][j4 * 4 + 0] + bias[c + 0];
            o.y = acc[i][j4 * 4 + 1] + bias[c + 1];
            o.z = acc[i][j4 * 4 + 2] + bias[c + 2];
            o.w = acc[i][j4 * 4 + 3] + bias[c + 3];
            *reinterpret_cast<float4*>(&O[(size_t)gr * HC + c]) = o;
        }
    }
}

// ---------------- split-bf16 tensor-core GEMM, cp.async double-buffered ----------------
#define GBM 64
#define GBN 128
#define GKB 32
#define AST 40
#define NIT (HC / GKB)
#define SZ_A (2 * GBM * AST)
#define SZ_B (2 * GBN * AST)
#define SMEM_MMA ((2 * SZ_A + 2 * SZ_B) * 2)

__device__ __forceinline__ void mma16816(float* c, const unsigned* a, const unsigned* b) {
    asm volatile(
        "mma.sync.aligned.m16n8k16.row.col.f32.bf16.bf16.f32 "
        "{%0,%1,%2,%3}, {%4,%5,%6,%7}, {%8,%9}, {%0,%1,%2,%3};\n"
        : "+f"(c[0]), "+f"(c[1]), "+f"(c[2]), "+f"(c[3])
        : "r"(a[0]), "r"(a[1]), "r"(a[2]), "r"(a[3]), "r"(b[0]), "r"(b[1]));
}

__global__ void __launch_bounds__(256) k_gemm_mma(
    int matbase,
    const float* __restrict__ b0, const float* __restrict__ b1) {
    extern __shared__ __nv_bfloat16 dyn[];
    int mat = matbase + blockIdx.z;
    const float* bias = blockIdx.z ? b1 : b0;
    float* O          = blockIdx.z ? g_xr : g_xl;
    const __nv_bfloat16* Wh = g_wh[mat];
    const __nv_bfloat16* Wl = g_wl[mat];

    unsigned base   = (unsigned)__cvta_generic_to_shared(dyn);
    unsigned addrAh = base;
    unsigned addrAl = addrAh + SZ_A * 2;
    unsigned addrBh = addrAl + SZ_A * 2;
    unsigned addrBl = addrBh + SZ_B * 2;

    int tid = threadIdx.x;
    int warp = tid >> 5, lane = tid & 31;
    int wm = (warp >> 2) * 32;
    int wn = (warp & 3) * 32;
    int row0 = blockIdx.x * GBM;
    int col0 = blockIdx.y * GBN;
    int group = lane >> 2, tg = lane & 3;

    int st_m  = tid >> 2, st_c8 = (tid & 3) * 8;
    int st_gr = row0 + st_m;
    int st_grc = st_gr < NN ? st_gr : 0;
    int st_sb  = (st_gr < NN) ? 16 : 0;

    int a_row = lane & 15;
    int a_k   = (lane >> 4) * 8;
    int b_n   = (lane & 7) + ((lane >> 4) & 1) * 8;
    int b_k   = ((lane >> 3) & 1) * 8;

    float acc[2][4][4];
#pragma unroll
    for (int mt = 0; mt < 2; ++mt)
#pragma unroll
        for (int nt = 0; nt < 4; ++nt)
#pragma unroll
            for (int q = 0; q < 4; ++q) acc[mt][nt][q] = 0.f;

    auto stage = [&](int k0, int buf) {
        unsigned da = (unsigned)(((buf * GBM + st_m) * AST + st_c8) * 2);
        cpa16(addrAh + da, &g_ah[(size_t)st_grc * HC + k0 + st_c8], st_sb);
        cpa16(addrAl + da, &g_al[(size_t)st_grc * HC + k0 + st_c8], st_sb);
#pragma unroll
        for (int t = 0; t < 2; ++t) {
            int idx = tid + t * 256;
            int n = idx >> 2, c8 = (idx & 3) * 8;
            size_t off = (size_t)(col0 + n) * HC + k0 + c8;
            unsigned db = (unsigned)(((buf * GBN + n) * AST + c8) * 2);
            cpa16(addrBh + db, &Wh[off], 16);
            cpa16(addrBl + db, &Wl[off], 16);
        }
        CP_COMMIT();
    };

    stage(0, 0);
    int cur = 0;
    for (int it = 0; it < NIT; ++it) {
        CP_WAIT0();
        __syncthreads();
        if (it + 1 < NIT) stage((it + 1) * GKB, cur ^ 1);
#pragma unroll
        for (int kk = 0; kk < GKB; kk += 16) {
            unsigned ah[2][4], al[2][4];
#pragma unroll
            for (int mt = 0; mt < 2; ++mt) {
                unsigned offA = (unsigned)((((cur * GBM) + wm + mt * 16 + a_row) * AST + kk + a_k) * 2);
                ldsm4(ah[mt][0], ah[mt][1], ah[mt][2], ah[mt][3], addrAh + offA);
                ldsm4(al[mt][0], al[mt][1], al[mt][2], al[mt][3], addrAl + offA);
            }
            unsigned bh[4][2], bl[4][2];
#pragma unroll
            for (int pr = 0; pr < 2; ++pr) {
                unsigned offB = (unsigned)((((cur * GBN) + wn + pr * 16 + b_n) * AST + kk + b_k) * 2);
                ldsm4(bh[2 * pr][0], bh[2 * pr][1], bh[2 * pr + 1][0], bh[2 * pr + 1][1],
                      addrBh + offB);
                ldsm4(bl[2 * pr][0], bl[2 * pr][1], bl[2 * pr + 1][0], bl[2 * pr + 1][1],
                      addrBl + offB);
            }
#pragma unroll
            for (int mt = 0; mt < 2; ++mt)
#pragma unroll
                for (int nt = 0; nt < 4; ++nt) {
                    mma16816(acc[mt][nt], ah[mt], bh[nt]);
                    mma16816(acc[mt][nt], ah[mt], bl[nt]);
                    mma16816(acc[mt][nt], al[mt], bh[nt]);
                }
        }
        __syncthreads();
        cur ^= 1;
    }
#pragma unroll
    for (int mt = 0; mt < 2; ++mt) {
#pragma unroll
        for (int nt = 0; nt < 4; ++nt) {
            int n = col0 + wn + nt * 8 + tg * 2;
            float2 bb = *reinterpret_cast<const float2*>(&bias[n]);
            int m = row0 + wm + mt * 16 + group;
            if (m < NN) {
                float2 o = make_float2(acc[mt][nt][0] + bb.x, acc[mt][nt][1] + bb.y);
                *reinterpret_cast<float2*>(&O[(size_t)m * HC + n]) = o;
            }
            int m2 = m + 8;
            if (m2 < NN) {
                float2 o = make_float2(acc[mt][nt][2] + bb.x, acc[mt][nt][3] + bb.y);
                *reinterpret_cast<float2*>(&O[(size_t)m2 * HC + n]) = o;
            }
        }
    }
}

// ---------------- fused GATv2 attention (R6: warp/node, pipelined, plain-exp) ----------------
__device__ __forceinline__ void attn_ld(const float* __restrict__ eattr,
                                        int eid, int s, int hc,
                                        ull* xl2, float* ea) {
    const float* pe = (eid < EE) ? (eattr + (size_t)eid * 8)
                                 : (g_sl + (size_t)(eid - EE) * 8);
    float4 e0 = *reinterpret_cast<const float4*>(pe);
    float4 e1 = *reinterpret_cast<const float4*>(pe + 4);
    ea[0] = e0.x; ea[1] = e0.y; ea[2] = e0.z; ea[3] = e0.w;
    ea[4] = e1.x; ea[5] = e1.y; ea[6] = e1.z; ea[7] = e1.w;
    ulonglong2 xa = *reinterpret_cast<const ulonglong2*>(&g_xl[(size_t)s * HC + hc]);
    ulonglong2 xb = *reinterpret_cast<const ulonglong2*>(&g_xl[(size_t)s * HC + hc + 4]);
    xl2[0] = xa.x; xl2[1] = xa.y; xl2[2] = xb.x; xl2[3] = xb.y;
}

__global__ void __launch_bounds__(128) k_attn(
    const float* __restrict__ eattr,
    const float* __restrict__ We, const float* __restrict__ att,
    const float* __restrict__ bias) {
    int gw = (blockIdx.x * blockDim.x + threadIdx.x) >> 5;
    int lane = threadIdx.x & 31;
    if (gw >= NN) return;
    int n = gw;
    int hc = lane * 8;

    ull we2[8][4];
#pragma unroll
    for (int k = 0; k < 8; ++k) {
        ulonglong2 u0 = *reinterpret_cast<const ulonglong2*>(&We[k * HC + hc]);
        ulonglong2 u1 = *reinterpret_cast<const ulonglong2*>(&We[k * HC + hc + 4]);
        we2[k][0] = u0.x; we2[k][1] = u0.y; we2[k][2] = u1.x; we2[k][3] = u1.y;
    }
    const ull c06 = dup2(0.6f), c04 = dup2(0.4f);
    ull att06[4], att04[4];
    {
        ulonglong2 a0 = *reinterpret_cast<const ulonglong2*>(&att[hc]);
        ulonglong2 a1 = *reinterpret_cast<const ulonglong2*>(&att[hc + 4]);
        ull a2[4] = {a0.x, a0.y, a1.x, a1.y};
#pragma unroll
        for (int q = 0; q < 4; ++q) {
            att06[q] = mul2(a2[q], c06);
            att04[q] = mul2(a2[q], c04);
        }
    }
    ull xr2[4];
    {
        ulonglong2 r0 = *reinterpret_cast<const ulonglong2*>(&g_xr[(size_t)n * HC + hc]);
        ulonglong2 r1 = *reinterpret_cast<const ulonglong2*>(&g_xr[(size_t)n * HC + hc + 4]);
        xr2[0] = r0.x; xr2[1] = r0.y; xr2[2] = r1.x; xr2[3] = r1.y;
    }

    int beg = g_rowptr[n], end = g_rowptr[n + 1];
    int eidA = g_eid[beg], sA = g_esrc[beg];
    int p1 = (beg + 1 < end) ? beg + 1 : beg;
    int eidB = g_eid[p1], sB = g_esrc[p1];
    ull xlC[4]; float eaC[8];
    attn_ld(eattr, eidA, sA, hc, xlC, eaC);

    float den = 0.f;
    ull acc2[4] = {0, 0, 0, 0};

    for (int p = beg; p < end; ++p) {
        int p2 = (p + 2 < end) ? p + 2 : p;
        int eidN2 = g_eid[p2], sN2 = g_esrc[p2];
        ull xlN[4]; float eaN[8];
        attn_ld(eattr, eidB, sB, hc, xlN, eaN);

        ull m2v[4];
#pragma unroll
        for (int q = 0; q < 4; ++q) m2v[q] = add2(xlC[q], xr2[q]);
#pragma unroll
        for (int k = 0; k < 8; ++k) {
            ull ek = dup2(eaC[k]);
#pragma unroll
            for (int q = 0; q < 4; ++q) m2v[q] = fma2(ek, we2[k][q], m2v[q]);
        }
        ull sc2 = 0;
#pragma unroll
        for (int q = 0; q < 4; ++q)
            sc2 = fma2(att04[q], abs2(m2v[q]), fma2(att06[q], m2v[q], sc2));
        float slo, shi;
        unpack2(sc2, slo, shi);
        float sc = slo + shi;
        sc += __shfl_xor_sync(0xffffffffu, sc, 1);
        sc += __shfl_xor_sync(0xffffffffu, sc, 2);

        float ex = __expf(sc);
        den += ex;
        ull exp2 = dup2(ex);
#pragma unroll
        for (int q = 0; q < 4; ++q) acc2[q] = fma2(exp2, xlC[q], acc2[q]);

#pragma unroll
        for (int q = 0; q < 4; ++q) xlC[q] = xlN[q];
#pragma unroll
        for (int k = 0; k < 8; ++k) eaC[k] = eaN[k];
        eidB = eidN2; sB = sN2;
    }

    float inv = 1.f / den;
    float4 b0 = *reinterpret_cast<const float4*>(&bias[hc]);
    float4 b1 = *reinterpret_cast<const float4*>(&bias[hc + 4]);
    float bb[8] = {b0.x, b0.y, b0.z, b0.w, b1.x, b1.y, b1.z, b1.w};
    __nv_bfloat16 oh[8], ol[8];
#pragma unroll
    for (int q = 0; q < 4; ++q) {
        float alo, ahi;
        unpack2(acc2[q], alo, ahi);
        float v0 = fmaf(alo, inv, bb[2 * q]);
        float v1 = fmaf(ahi, inv, bb[2 * q + 1]);
        v0 = (v0 > 0.f) ? v0 : 0.2f * v0;
        v1 = (v1 > 0.f) ? v1 : 0.2f * v1;
        splitf(v0, oh[2 * q], ol[2 * q]);
        splitf(v1, oh[2 * q + 1], ol[2 * q + 1]);
    }
    uint4 ph, pl;
    {
        unsigned uh[4], ul[4];
#pragma unroll
        for (int q = 0; q < 4; ++q) {
            __nv_bfloat162 th = __halves2bfloat162(oh[2 * q], oh[2 * q + 1]);
            __nv_bfloat162 tl = __halves2bfloat162(ol[2 * q], ol[2 * q + 1]);
            uh[q] = *reinterpret_cast<unsigned*>(&th);
            ul[q] = *reinterpret_cast<unsigned*>(&tl);
        }
        ph = make_uint4(uh[0], uh[1], uh[2], uh[3]);
        pl = make_uint4(ul[0], ul[1], ul[2], ul[3]);
    }
    *reinterpret_cast<uint4*>(&g_ah[(size_t)n * HC + hc]) = ph;
    *reinterpret_cast<uint4*>(&g_al[(size_t)n * HC + hc]) = pl;
}

// ---------------- fused MLP head (warp per node) ----------------
__global__ void __launch_bounds__(256) k_mlp(
    const float* __restrict__ W0, const float* __restrict__ b0,
    const float* __restrict__ W1, const float* __restrict__ b1,
    const float* __restrict__ W2, const float* __restrict__ b2,
    const float* __restrict__ W3, const float* __restrict__ b3,
    float* __restrict__ out) {
    __shared__ float sW0[16 * 256];
    __shared__ float sW1[256], sW2[256], sW3[64];
    __shared__ float sb[52];
    int tid = threadIdx.x;
    {
        int k = tid;
#pragma unroll
        for (int j = 0; j < 16; ++j) sW0[j * 256 + k] = W0[k * 16 + j];
    }
    if (tid < 256) { sW1[tid] = W1[tid]; sW2[tid] = W2[tid]; }
    if (tid < 64)  sW3[tid] = W3[tid];
    if (tid < 16)  { sb[tid] = b0[tid]; sb[16 + tid] = b1[tid]; sb[32 + tid] = b2[tid]; }
    if (tid < 4)   sb[48 + tid] = b3[tid];
    __syncthreads();

    int gw = (blockIdx.x * blockDim.x + tid) >> 5;
    int lane = tid & 31;
    if (gw >= NN) return;
    int n = gw;

    float hin[8];
    {
        uint4 uh = *reinterpret_cast<const uint4*>(&g_ah[(size_t)n * HC + lane * 8]);
        uint4 ul = *reinterpret_cast<const uint4*>(&g_al[(size_t)n * HC + lane * 8]);
        unsigned ah[4] = {uh.x, uh.y, uh.z, uh.w};
        unsigned al[4] = {ul.x, ul.y, ul.z, ul.w};
#pragma unroll
        for (int q = 0; q < 4; ++q) {
            float2 fh = __bfloat1622float2(*reinterpret_cast<__nv_bfloat162*>(&ah[q]));
            float2 fl = __bfloat1622float2(*reinterpret_cast<__nv_bfloat162*>(&al[q]));
            hin[2 * q]     = fh.x + fl.x;
            hin[2 * q + 1] = fh.y + fl.y;
        }
    }
    float v[16];
#pragma unroll
    for (int j = 0; j < 16; ++j) {
        float4 w0 = *reinterpret_cast<float4*>(&sW0[j * 256 + lane * 8]);
        float4 w1 = *reinterpret_cast<float4*>(&sW0[j * 256 + lane * 8 + 4]);
        float p = hin[0] * w0.x;
        p = fmaf(hin[1], w0.y, p); p = fmaf(hin[2], w0.z, p); p = fmaf(hin[3], w0.w, p);
        p = fmaf(hin[4], w1.x, p); p = fmaf(hin[5], w1.y, p);
        p = fmaf(hin[6], w1.z, p); p = fmaf(hin[7], w1.w, p);
        v[j] = p;
    }
#pragma unroll
    for (int j = 0; j < 16; ++j) {
#pragma unroll
        for (int d = 16; d > 0; d >>= 1) v[j] += __shfl_xor_sync(0xffffffffu, v[j], d);
        v[j] = fmaxf(v[j] + sb[j], 0.f);
    }
    float u[16];
#pragma unroll
    for (int j = 0; j < 16; ++j) {
        float p = sb[16 + j];
#pragma unroll
        for (int k = 0; k < 16; ++k) p = fmaf(v[k], sW1[k * 16 + j], p);
        u[j] = fmaxf(p, 0.f);
    }
#pragma unroll
    for (int j = 0; j < 16; ++j) {
        float p = sb[32 + j];
#pragma unroll
        for (int k = 0; k < 16; ++k) p = fmaf(u[k], sW2[k * 16 + j], p);
        v[j] = fmaxf(p, 0.f);
    }
    if (lane < 4) {
        float p = sb[48 + lane];
#pragma unroll
        for (int k = 0; k < 16; ++k) p = fmaf(v[k], sW3[k * 4 + lane], p);
        out[n * 4 + lane] = p;
    }
}

// ---------------- launch ----------------
extern "C" void kernel_launch(void* const* d_in, const int* in_sizes, int n_in,
                              void* d_out, int out_size) {
    const float* x     = (const float*)d_in[0];
    const int*   ei    = (const int*)d_in[1];
    const float* eattr = (const float*)d_in[2];
    const float* P[29];
    for (int i = 0; i < 29; ++i) P[i] = (const float*)d_in[3 + i];
    const int* src = ei;
    const int* dst = ei + EE;
    float* out = (float*)d_out;

    cudaFuncSetAttribute(k_gemm_mma, cudaFuncAttributeMaxDynamicSharedMemorySize, SMEM_MMA);

    // weight split (layers 1-2: Wl1, Wr1, Wl2, Wr2) + counter zeroing
    dim3 gsw(HC * HC / 256, 1, 4);
    k_splitw<<<gsw, 256>>>(P[7], P[9], P[14], P[16]);

    // CSR
    k_count<<<(EE + 255) / 256, 256>>>(dst);
    k_scan<<<1, 1024>>>();
    k_scatter<<<(ET + 255) / 256, 256>>>(src, dst);
    k_slmean<<<(NN * 32 + 255) / 256, 256>>>(eattr);

    dim3 gg((NN + BM - 1) / BM, HC / BN, 2);
    dim3 gm((NN + GBM - 1) / GBM, HC / GBN, 2);

    // layer 0 (K=16, input = x)
    k_gemm<<<gg, 256>>>(x, P[0], P[1], P[2], P[3]);
    k_attn<<<(NN * 32 + 127) / 128, 128>>>(eattr, P[4], P[5], P[6]);
    // layer 1 (K=256)
    k_gemm_mma<<<gm, 256, SMEM_MMA>>>(0, P[8], P[10]);
    k_attn<<<(NN * 32 + 127) / 128, 128>>>(eattr, P[11], P[12], P[13]);
    // layer 2
    k_gemm_mma<<<gm, 256, SMEM_MMA>>>(2, P[15], P[17]);
    k_attn<<<(NN * 32 + 127) / 128, 128>>>(eattr, P[18], P[19], P[20]);

    // MLP head
    k_mlp<<<(NN * 32 + 255) / 256, 256>>>(P[21], P[22], P[23], P[24],
                                          P[25], P[26], P[27], P[28], out);
}

// round 17
// speedup vs baseline: 1.1677x; 1.0136x over previous
#include <cuda_runtime.h>
#include <cuda_bf16.h>
#include <math_constants.h>

#define NN 20000
#define EE 320000
#define ET (EE + NN)
#define HC 256

// ---------------- scratch (device globals; no allocation) ----------------
__device__ float g_sl[(size_t)NN * 8];          // self-loop edge attrs
__device__ float g_xl[(size_t)NN * HC];         // source transform (fp32)
__device__ float g_xr[(size_t)NN * HC];         // dest transform   (fp32)
__device__ __nv_bfloat16 g_ah[(size_t)NN * HC]; // node features hi
__device__ __nv_bfloat16 g_al[(size_t)NN * HC]; // node features lo
__device__ __nv_bfloat16 g_wh[4][HC * HC];      // transposed weight hi  [n][k]
__device__ __nv_bfloat16 g_wl[4][HC * HC];      // transposed weight lo  [n][k]
__device__ int   g_deg[NN];
__device__ int   g_fill[NN];
__device__ int   g_rowptr[NN + 1];
__device__ int   g_eid[ET];
__device__ int   g_esrc[ET];

typedef unsigned long long ull;

__device__ __forceinline__ void splitf(float v, __nv_bfloat16& h, __nv_bfloat16& l) {
    h = __float2bfloat16(v);
    l = __float2bfloat16(v - __bfloat162float(h));
}

// ---- f32x2 packed helpers ----
__device__ __forceinline__ ull dup2(float s) {
    ull r; asm("mov.b64 %0, {%1, %1};" : "=l"(r) : "f"(s)); return r;
}
__device__ __forceinline__ ull fma2(ull a, ull b, ull c) {
    ull r; asm("fma.rn.f32x2 %0, %1, %2, %3;" : "=l"(r) : "l"(a), "l"(b), "l"(c)); return r;
}
__device__ __forceinline__ ull mul2(ull a, ull b) {
    ull r; asm("mul.rn.f32x2 %0, %1, %2;" : "=l"(r) : "l"(a), "l"(b)); return r;
}
__device__ __forceinline__ ull add2(ull a, ull b) {
    ull r; asm("add.rn.f32x2 %0, %1, %2;" : "=l"(r) : "l"(a), "l"(b)); return r;
}
__device__ __forceinline__ ull abs2(ull a) {
    ull r; asm("and.b64 %0, %1, 0x7FFFFFFF7FFFFFFF;" : "=l"(r) : "l"(a)); return r;
}
__device__ __forceinline__ void unpack2(ull v, float& lo, float& hi) {
    asm("mov.b64 {%0, %1}, %2;" : "=f"(lo), "=f"(hi) : "l"(v));
}

// ---- ldmatrix / cp.async ----
__device__ __forceinline__ void ldsm4(unsigned& r0, unsigned& r1, unsigned& r2, unsigned& r3,
                                      unsigned addr) {
    asm volatile("ldmatrix.sync.aligned.m8n8.x4.shared.b16 {%0,%1,%2,%3}, [%4];"
                 : "=r"(r0), "=r"(r1), "=r"(r2), "=r"(r3) : "r"(addr));
}
__device__ __forceinline__ void cpa16(unsigned sa, const void* ga, int srcbytes) {
    asm volatile("cp.async.ca.shared.global [%0], [%1], 16, %2;"
                 :: "r"(sa), "l"(ga), "r"(srcbytes));
}
#define CP_COMMIT() asm volatile("cp.async.commit_group;")
#define CP_WAIT0()  asm volatile("cp.async.wait_group 0;")

// ---------------- weight split + transpose (+ counter zeroing) ----------------
__global__ void k_splitw(const float* __restrict__ Wa, const float* __restrict__ Wb,
                         const float* __restrict__ Wc, const float* __restrict__ Wd) {
    const float* W = (blockIdx.z == 0) ? Wa : (blockIdx.z == 1) ? Wb
                   : (blockIdx.z == 2) ? Wc : Wd;
    int idx = blockIdx.x * blockDim.x + threadIdx.x;
    int k = idx >> 8, n = idx & 255;
    float v = W[idx];
    __nv_bfloat16 h, l;
    splitf(v, h, l);
    g_wh[blockIdx.z][n * HC + k] = h;
    g_wl[blockIdx.z][n * HC + k] = l;
    if (blockIdx.z == 0 && idx < NN) { g_deg[idx] = 0; g_fill[idx] = 0; }
}

// ---------------- CSR build ----------------
__global__ void k_count(const int* __restrict__ dst) {
    int e = blockIdx.x * blockDim.x + threadIdx.x;
    if (e < EE) atomicAdd(&g_deg[dst[e]], 1);
}

#define NCHUNK 20
__global__ void __launch_bounds__(1024) k_scan() {
    __shared__ int wsum[32];
    __shared__ int woff[32];
    __shared__ int s_carry;
    int tid = threadIdx.x, lane = tid & 31, wid = tid >> 5;
    int v[NCHUNK];
#pragma unroll
    for (int j = 0; j < NCHUNK; ++j) {
        int i = j * 1024 + tid;
        v[j] = (i < NN) ? (g_deg[i] + 1) : 0;
    }
    if (tid == 0) { g_rowptr[0] = 0; s_carry = 0; }
    __syncthreads();
#pragma unroll
    for (int j = 0; j < NCHUNK; ++j) {
        int x = v[j];
#pragma unroll
        for (int off = 1; off < 32; off <<= 1) {
            int t = __shfl_up_sync(0xffffffffu, x, off);
            if (lane >= off) x += t;
        }
        if (lane == 31) wsum[wid] = x;
        __syncthreads();
        if (wid == 0) {
            int s = wsum[lane];
            int y = s;
#pragma unroll
            for (int off = 1; off < 32; off <<= 1) {
                int t = __shfl_up_sync(0xffffffffu, y, off);
                if (lane >= off) y += t;
            }
            woff[lane] = y - s;
        }
        __syncthreads();
        int incl = x + woff[wid] + s_carry;
        int i = j * 1024 + tid;
        if (i < NN) g_rowptr[i + 1] = incl;
        __syncthreads();
        if (tid == 1023) s_carry = incl;
        __syncthreads();
    }
}

__global__ void k_scatter(const int* __restrict__ src, const int* __restrict__ dst) {
    int e = blockIdx.x * blockDim.x + threadIdx.x;
    if (e >= ET) return;
    int s, d;
    if (e < EE) { s = src[e]; d = dst[e]; }
    else        { s = e - EE; d = s; }
    int pos = g_rowptr[d] + atomicAdd(&g_fill[d], 1);
    g_eid[pos]  = e;
    g_esrc[pos] = s;
}

// self-loop attr = mean of incoming edge attrs (warp per node, no atomics)
__global__ void __launch_bounds__(256) k_slmean(const float* __restrict__ eattr) {
    int gw = (blockIdx.x * blockDim.x + threadIdx.x) >> 5;
    int lane = threadIdx.x & 31;
    if (gw >= NN) return;
    int beg = g_rowptr[gw], end = g_rowptr[gw + 1];
    int slot = lane >> 3, ch = lane & 7;
    float v = 0.f;
    for (int p = beg + slot; p < end; p += 4) {
        int eid = g_eid[p];
        if (eid < EE) v += eattr[(size_t)eid * 8 + ch];
    }
    v += __shfl_xor_sync(0xffffffffu, v, 8);
    v += __shfl_xor_sync(0xffffffffu, v, 16);
    if (lane < 8) {
        int dg = end - beg - 1;
        float inv = 1.f / (float)(dg > 1 ? dg : 1);
        g_sl[(size_t)gw * 8 + lane] = v * inv;
    }
}

// ---------------- fp32 GEMM (layer 0 only, K=16), xl+xr fused via z ----------------
#define BM 128
#define BN 128
#define BK 16
__global__ void __launch_bounds__(256) k_gemm(
    const float* __restrict__ A,
    const float* __restrict__ W0, const float* __restrict__ b0,
    const float* __restrict__ W1, const float* __restrict__ b1) {
    __shared__ float As[BK][BM + 4];
    __shared__ float Bs[BK][BN];
    const float* W    = blockIdx.z ? W1 : W0;
    const float* bias = blockIdx.z ? b1 : b0;
    float* O          = blockIdx.z ? g_xr : g_xl;
    const int K = 16;
    int tid = threadIdx.x;
    int tx = tid & 15, ty = tid >> 4;
    int row0 = blockIdx.x * BM;
    int col0 = blockIdx.y * BN;
    float acc[8][8];
#pragma unroll
    for (int i = 0; i < 8; ++i)
#pragma unroll
        for (int j = 0; j < 8; ++j) acc[i][j] = 0.f;

#pragma unroll
    for (int i = 0; i < 2; ++i) {
        int f = tid * 2 + i;
        int r = f >> 2, c4 = (f & 3) * 4;
        int gr = row0 + r;
        float4 v = make_float4(0.f, 0.f, 0.f, 0.f);
        if (gr < NN) v = *reinterpret_cast<const float4*>(&A[(size_t)gr * K + c4]);
        As[c4 + 0][r] = v.x; As[c4 + 1][r] = v.y;
        As[c4 + 2][r] = v.z; As[c4 + 3][r] = v.w;
    }
#pragma unroll
    for (int i = 0; i < 2; ++i) {
        int f = tid * 2 + i;
        int r = f >> 5, c4 = (f & 31) * 4;
        *reinterpret_cast<float4*>(&Bs[r][c4]) =
            *reinterpret_cast<const float4*>(&W[(size_t)r * HC + col0 + c4]);
    }
    __syncthreads();
#pragma unroll
    for (int kk = 0; kk < BK; ++kk) {
        float a[8], b[8];
        *reinterpret_cast<float4*>(&a[0]) = *reinterpret_cast<float4*>(&As[kk][ty * 8]);
        *reinterpret_cast<float4*>(&a[4]) = *reinterpret_cast<float4*>(&As[kk][ty * 8 + 4]);
        *reinterpret_cast<float4*>(&b[0]) = *reinterpret_cast<float4*>(&Bs[kk][tx * 8]);
        *reinterpret_cast<float4*>(&b[4]) = *reinterpret_cast<float4*>(&Bs[kk][tx * 8 + 4]);
#pragma unroll
        for (int i = 0; i < 8; ++i)
#pragma unroll
            for (int j = 0; j < 8; ++j)
                acc[i][j] = fmaf(a[i], b[j], acc[i][j]);
    }
#pragma unroll
    for (int i = 0; i < 8; ++i) {
        int gr = row0 + ty * 8 + i;
        if (gr >= NN) continue;
#pragma unroll
        for (int j4 = 0; j4 < 2; ++j4) {
            int c = col0 + tx * 8 + j4 * 4;
            float4 o;
            o.x = acc[i][j4 * 4 + 0] + bias[c + 0];
            o.y = acc[i][j4 * 4 + 1] + bias[c + 1];
            o.z = acc[i][j4 * 4 + 2] + bias[c + 2];
            o.w = acc[i][j4 * 4 + 3] + bias[c + 3];
            *reinterpret_cast<float4*>(&O[(size_t)gr * HC + c]) = o;
        }
    }
}

// ---------------- split-bf16 tensor-core GEMM, cp.async double-buffered ----------------
// GBM=128: each warp covers M=64 x N=32 -> 48 MMAs per 12 ldsm4 (was 24 per 8)
#define GBM 128
#define GBN 128
#define GKB 32
#define AST 40
#define NIT (HC / GKB)
#define SZ_A (2 * GBM * AST)
#define SZ_B (2 * GBN * AST)
#define SMEM_MMA ((2 * SZ_A + 2 * SZ_B) * 2)   // 81920 bytes

__device__ __forceinline__ void mma16816(float* c, const unsigned* a, const unsigned* b) {
    asm volatile(
        "mma.sync.aligned.m16n8k16.row.col.f32.bf16.bf16.f32 "
        "{%0,%1,%2,%3}, {%4,%5,%6,%7}, {%8,%9}, {%0,%1,%2,%3};\n"
        : "+f"(c[0]), "+f"(c[1]), "+f"(c[2]), "+f"(c[3])
        : "r"(a[0]), "r"(a[1]), "r"(a[2]), "r"(a[3]), "r"(b[0]), "r"(b[1]));
}

__global__ void __launch_bounds__(256) k_gemm_mma(
    int matbase,
    const float* __restrict__ b0, const float* __restrict__ b1) {
    extern __shared__ __nv_bfloat16 dyn[];
    int mat = matbase + blockIdx.z;
    const float* bias = blockIdx.z ? b1 : b0;
    float* O          = blockIdx.z ? g_xr : g_xl;
    const __nv_bfloat16* Wh = g_wh[mat];
    const __nv_bfloat16* Wl = g_wl[mat];

    unsigned base   = (unsigned)__cvta_generic_to_shared(dyn);
    unsigned addrAh = base;
    unsigned addrAl = addrAh + SZ_A * 2;
    unsigned addrBh = addrAl + SZ_A * 2;
    unsigned addrBl = addrBh + SZ_B * 2;

    int tid = threadIdx.x;
    int warp = tid >> 5, lane = tid & 31;
    int wm = (warp >> 2) * 64;          // 0 or 64
    int wn = (warp & 3) * 32;           // 0,32,64,96
    int row0 = blockIdx.x * GBM;
    int col0 = blockIdx.y * GBN;
    int group = lane >> 2, tg = lane & 3;

    int a_row = lane & 15;
    int a_k   = (lane >> 4) * 8;
    int b_n   = (lane & 7) + ((lane >> 4) & 1) * 8;
    int b_k   = ((lane >> 3) & 1) * 8;

    float acc[4][4][4];
#pragma unroll
    for (int mt = 0; mt < 4; ++mt)
#pragma unroll
        for (int nt = 0; nt < 4; ++nt)
#pragma unroll
            for (int q = 0; q < 4; ++q) acc[mt][nt][q] = 0.f;

    auto stage = [&](int k0, int buf) {
        // A: 128 rows x 32 bf16 (hi & lo)
#pragma unroll
        for (int t = 0; t < 2; ++t) {
            int idx = tid + t * 256;
            int m = idx >> 2, c8 = (idx & 3) * 8;
            int gr = row0 + m;
            int grc = gr < NN ? gr : 0;
            int sb  = (gr < NN) ? 16 : 0;
            unsigned da = (unsigned)(((buf * GBM + m) * AST + c8) * 2);
            cpa16(addrAh + da, &g_ah[(size_t)grc * HC + k0 + c8], sb);
            cpa16(addrAl + da, &g_al[(size_t)grc * HC + k0 + c8], sb);
        }
        // B: 128 rows x 32 bf16 (hi & lo)
#pragma unroll
        for (int t = 0; t < 2; ++t) {
            int idx = tid + t * 256;
            int n = idx >> 2, c8 = (idx & 3) * 8;
            size_t off = (size_t)(col0 + n) * HC + k0 + c8;
            unsigned db = (unsigned)(((buf * GBN + n) * AST + c8) * 2);
            cpa16(addrBh + db, &Wh[off], 16);
            cpa16(addrBl + db, &Wl[off], 16);
        }
        CP_COMMIT();
    };

    stage(0, 0);
    int cur = 0;
    for (int it = 0; it < NIT; ++it) {
        CP_WAIT0();
        __syncthreads();
        if (it + 1 < NIT) stage((it + 1) * GKB, cur ^ 1);
#pragma unroll
        for (int kk = 0; kk < GKB; kk += 16) {
            unsigned ah[4][4], al[4][4];
#pragma unroll
            for (int mt = 0; mt < 4; ++mt) {
                unsigned offA = (unsigned)((((cur * GBM) + wm + mt * 16 + a_row) * AST + kk + a_k) * 2);
                ldsm4(ah[mt][0], ah[mt][1], ah[mt][2], ah[mt][3], addrAh + offA);
                ldsm4(al[mt][0], al[mt][1], al[mt][2], al[mt][3], addrAl + offA);
            }
            unsigned bh[4][2], bl[4][2];
#pragma unroll
            for (int pr = 0; pr < 2; ++pr) {
                unsigned offB = (unsigned)((((cur * GBN) + wn + pr * 16 + b_n) * AST + kk + b_k) * 2);
                ldsm4(bh[2 * pr][0], bh[2 * pr][1], bh[2 * pr + 1][0], bh[2 * pr + 1][1],
                      addrBh + offB);
                ldsm4(bl[2 * pr][0], bl[2 * pr][1], bl[2 * pr + 1][0], bl[2 * pr + 1][1],
                      addrBl + offB);
            }
#pragma unroll
            for (int mt = 0; mt < 4; ++mt)
#pragma unroll
                for (int nt = 0; nt < 4; ++nt) {
                    mma16816(acc[mt][nt], ah[mt], bh[nt]);
                    mma16816(acc[mt][nt], ah[mt], bl[nt]);
                    mma16816(acc[mt][nt], al[mt], bh[nt]);
                }
        }
        __syncthreads();
        cur ^= 1;
    }
#pragma unroll
    for (int mt = 0; mt < 4; ++mt) {
#pragma unroll
        for (int nt = 0; nt < 4; ++nt) {
            int n = col0 + wn + nt * 8 + tg * 2;
            float2 bb = *reinterpret_cast<const float2*>(&bias[n]);
            int m = row0 + wm + mt * 16 + group;
            if (m < NN) {
                float2 o = make_float2(acc[mt][nt][0] + bb.x, acc[mt][nt][1] + bb.y);
                *reinterpret_cast<float2*>(&O[(size_t)m * HC + n]) = o;
            }
            int m2 = m + 8;
            if (m2 < NN) {
                float2 o = make_float2(acc[mt][nt][2] + bb.x, acc[mt][nt][3] + bb.y);
                *reinterpret_cast<float2*>(&O[(size_t)m2 * HC + n]) = o;
            }
        }
    }
}

// ---------------- fused GATv2 attention (R6: warp/node, pipelined, plain-exp) ----------------
__device__ __forceinline__ void attn_ld(const float* __restrict__ eattr,
                                        int eid, int s, int hc,
                                        ull* xl2, float* ea) {
    const float* pe = (eid < EE) ? (eattr + (size_t)eid * 8)
                                 : (g_sl + (size_t)(eid - EE) * 8);
    float4 e0 = *reinterpret_cast<const float4*>(pe);
    float4 e1 = *reinterpret_cast<const float4*>(pe + 4);
    ea[0] = e0.x; ea[1] = e0.y; ea[2] = e0.z; ea[3] = e0.w;
    ea[4] = e1.x; ea[5] = e1.y; ea[6] = e1.z; ea[7] = e1.w;
    ulonglong2 xa = *reinterpret_cast<const ulonglong2*>(&g_xl[(size_t)s * HC + hc]);
    ulonglong2 xb = *reinterpret_cast<const ulonglong2*>(&g_xl[(size_t)s * HC + hc + 4]);
    xl2[0] = xa.x; xl2[1] = xa.y; xl2[2] = xb.x; xl2[3] = xb.y;
}

__global__ void __launch_bounds__(128) k_attn(
    const float* __restrict__ eattr,
    const float* __restrict__ We, const float* __restrict__ att,
    const float* __restrict__ bias) {
    int gw = (blockIdx.x * blockDim.x + threadIdx.x) >> 5;
    int lane = threadIdx.x & 31;
    if (gw >= NN) return;
    int n = gw;
    int hc = lane * 8;

    ull we2[8][4];
#pragma unroll
    for (int k = 0; k < 8; ++k) {
        ulonglong2 u0 = *reinterpret_cast<const ulonglong2*>(&We[k * HC + hc]);
        ulonglong2 u1 = *reinterpret_cast<const ulonglong2*>(&We[k * HC + hc + 4]);
        we2[k][0] = u0.x; we2[k][1] = u0.y; we2[k][2] = u1.x; we2[k][3] = u1.y;
    }
    const ull c06 = dup2(0.6f), c04 = dup2(0.4f);
    ull att06[4], att04[4];
    {
        ulonglong2 a0 = *reinterpret_cast<const ulonglong2*>(&att[hc]);
        ulonglong2 a1 = *reinterpret_cast<const ulonglong2*>(&att[hc + 4]);
        ull a2[4] = {a0.x, a0.y, a1.x, a1.y};
#pragma unroll
        for (int q = 0; q < 4; ++q) {
            att06[q] = mul2(a2[q], c06);
            att04[q] = mul2(a2[q], c04);
        }
    }
    ull xr2[4];
    {
        ulonglong2 r0 = *reinterpret_cast<const ulonglong2*>(&g_xr[(size_t)n * HC + hc]);
        ulonglong2 r1 = *reinterpret_cast<const ulonglong2*>(&g_xr[(size_t)n * HC + hc + 4]);
        xr2[0] = r0.x; xr2[1] = r0.y; xr2[2] = r1.x; xr2[3] = r1.y;
    }

    int beg = g_rowptr[n], end = g_rowptr[n + 1];
    int eidA = g_eid[beg], sA = g_esrc[beg];
    int p1 = (beg + 1 < end) ? beg + 1 : beg;
    int eidB = g_eid[p1], sB = g_esrc[p1];
    ull xlC[4]; float eaC[8];
    attn_ld(eattr, eidA, sA, hc, xlC, eaC);

    float den = 0.f;
    ull acc2[4] = {0, 0, 0, 0};

    for (int p = beg; p < end; ++p) {
        int p2 = (p + 2 < end) ? p + 2 : p;
        int eidN2 = g_eid[p2], sN2 = g_esrc[p2];
        ull xlN[4]; float eaN[8];
        attn_ld(eattr, eidB, sB, hc, xlN, eaN);

        ull m2v[4];
#pragma unroll
        for (int q = 0; q < 4; ++q) m2v[q] = add2(xlC[q], xr2[q]);
#pragma unroll
        for (int k = 0; k < 8; ++k) {
            ull ek = dup2(eaC[k]);
#pragma unroll
            for (int q = 0; q < 4; ++q) m2v[q] = fma2(ek, we2[k][q], m2v[q]);
        }
        ull sc2 = 0;
#pragma unroll
        for (int q = 0; q < 4; ++q)
            sc2 = fma2(att04[q], abs2(m2v[q]), fma2(att06[q], m2v[q], sc2));
        float slo, shi;
        unpack2(sc2, slo, shi);
        float sc = slo + shi;
        sc += __shfl_xor_sync(0xffffffffu, sc, 1);
        sc += __shfl_xor_sync(0xffffffffu, sc, 2);

        float ex = __expf(sc);
        den += ex;
        ull exp2 = dup2(ex);
#pragma unroll
        for (int q = 0; q < 4; ++q) acc2[q] = fma2(exp2, xlC[q], acc2[q]);

#pragma unroll
        for (int q = 0; q < 4; ++q) xlC[q] = xlN[q];
#pragma unroll
        for (int k = 0; k < 8; ++k) eaC[k] = eaN[k];
        eidB = eidN2; sB = sN2;
    }

    float inv = 1.f / den;
    float4 b0 = *reinterpret_cast<const float4*>(&bias[hc]);
    float4 b1 = *reinterpret_cast<const float4*>(&bias[hc + 4]);
    float bb[8] = {b0.x, b0.y, b0.z, b0.w, b1.x, b1.y, b1.z, b1.w};
    __nv_bfloat16 oh[8], ol[8];
#pragma unroll
    for (int q = 0; q < 4; ++q) {
        float alo, ahi;
        unpack2(acc2[q], alo, ahi);
        float v0 = fmaf(alo, inv, bb[2 * q]);
        float v1 = fmaf(ahi, inv, bb[2 * q + 1]);
        v0 = (v0 > 0.f) ? v0 : 0.2f * v0;
        v1 = (v1 > 0.f) ? v1 : 0.2f * v1;
        splitf(v0, oh[2 * q], ol[2 * q]);
        splitf(v1, oh[2 * q + 1], ol[2 * q + 1]);
    }
    uint4 ph, pl;
    {
        unsigned uh[4], ul[4];
#pragma unroll
        for (int q = 0; q < 4; ++q) {
            __nv_bfloat162 th = __halves2bfloat162(oh[2 * q], oh[2 * q + 1]);
            __nv_bfloat162 tl = __halves2bfloat162(ol[2 * q], ol[2 * q + 1]);
            uh[q] = *reinterpret_cast<unsigned*>(&th);
            ul[q] = *reinterpret_cast<unsigned*>(&tl);
        }
        ph = make_uint4(uh[0], uh[1], uh[2], uh[3]);
        pl = make_uint4(ul[0], ul[1], ul[2], ul[3]);
    }
    *reinterpret_cast<uint4*>(&g_ah[(size_t)n * HC + hc]) = ph;
    *reinterpret_cast<uint4*>(&g_al[(size_t)n * HC + hc]) = pl;
}

// ---------------- fused MLP head (warp per node) ----------------
__global__ void __launch_bounds__(256) k_mlp(
    const float* __restrict__ W0, const float* __restrict__ b0,
    const float* __restrict__ W1, const float* __restrict__ b1,
    const float* __restrict__ W2, const float* __restrict__ b2,
    const float* __restrict__ W3, const float* __restrict__ b3,
    float* __restrict__ out) {
    __shared__ float sW0[16 * 256];
    __shared__ float sW1[256], sW2[256], sW3[64];
    __shared__ float sb[52];
    int tid = threadIdx.x;
    {
        int k = tid;
#pragma unroll
        for (int j = 0; j < 16; ++j) sW0[j * 256 + k] = W0[k * 16 + j];
    }
    if (tid < 256) { sW1[tid] = W1[tid]; sW2[tid] = W2[tid]; }
    if (tid < 64)  sW3[tid] = W3[tid];
    if (tid < 16)  { sb[tid] = b0[tid]; sb[16 + tid] = b1[tid]; sb[32 + tid] = b2[tid]; }
    if (tid < 4)   sb[48 + tid] = b3[tid];
    __syncthreads();

    int gw = (blockIdx.x * blockDim.x + tid) >> 5;
    int lane = tid & 31;
    if (gw >= NN) return;
    int n = gw;

    float hin[8];
    {
        uint4 uh = *reinterpret_cast<const uint4*>(&g_ah[(size_t)n * HC + lane * 8]);
        uint4 ul = *reinterpret_cast<const uint4*>(&g_al[(size_t)n * HC + lane * 8]);
        unsigned ah[4] = {uh.x, uh.y, uh.z, uh.w};
        unsigned al[4] = {ul.x, ul.y, ul.z, ul.w};
#pragma unroll
        for (int q = 0; q < 4; ++q) {
            float2 fh = __bfloat1622float2(*reinterpret_cast<__nv_bfloat162*>(&ah[q]));
            float2 fl = __bfloat1622float2(*reinterpret_cast<__nv_bfloat162*>(&al[q]));
            hin[2 * q]     = fh.x + fl.x;
            hin[2 * q + 1] = fh.y + fl.y;
        }
    }
    float v[16];
#pragma unroll
    for (int j = 0; j < 16; ++j) {
        float4 w0 = *reinterpret_cast<float4*>(&sW0[j * 256 + lane * 8]);
        float4 w1 = *reinterpret_cast<float4*>(&sW0[j * 256 + lane * 8 + 4]);
        float p = hin[0] * w0.x;
        p = fmaf(hin[1], w0.y, p); p = fmaf(hin[2], w0.z, p); p = fmaf(hin[3], w0.w, p);
        p = fmaf(hin[4], w1.x, p); p = fmaf(hin[5], w1.y, p);
        p = fmaf(hin[6], w1.z, p); p = fmaf(hin[7], w1.w, p);
        v[j] = p;
    }
#pragma unroll
    for (int j = 0; j < 16; ++j) {
#pragma unroll
        for (int d = 16; d > 0; d >>= 1) v[j] += __shfl_xor_sync(0xffffffffu, v[j], d);
        v[j] = fmaxf(v[j] + sb[j], 0.f);
    }
    float u[16];
#pragma unroll
    for (int j = 0; j < 16; ++j) {
        float p = sb[16 + j];
#pragma unroll
        for (int k = 0; k < 16; ++k) p = fmaf(v[k], sW1[k * 16 + j], p);
        u[j] = fmaxf(p, 0.f);
    }
#pragma unroll
    for (int j = 0; j < 16; ++j) {
        float p = sb[32 + j];
#pragma unroll
        for (int k = 0; k < 16; ++k) p = fmaf(u[k], sW2[k * 16 + j], p);
        v[j] = fmaxf(p, 0.f);
    }
    if (lane < 4) {
        float p = sb[48 + lane];
#pragma unroll
        for (int k = 0; k < 16; ++k) p = fmaf(v[k], sW3[k * 4 + lane], p);
        out[n * 4 + lane] = p;
    }
}

// ---------------- launch ----------------
extern "C" void kernel_launch(void* const* d_in, const int* in_sizes, int n_in,
                              void* d_out, int out_size) {
    const float* x     = (const float*)d_in[0];
    const int*   ei    = (const int*)d_in[1];
    const float* eattr = (const float*)d_in[2];
    const float* P[29];
    for (int i = 0; i < 29; ++i) P[i] = (const float*)d_in[3 + i];
    const int* src = ei;
    const int* dst = ei + EE;
    float* out = (float*)d_out;

    cudaFuncSetAttribute(k_gemm_mma, cudaFuncAttributeMaxDynamicSharedMemorySize, SMEM_MMA);

    // weight split (layers 1-2: Wl1, Wr1, Wl2, Wr2) + counter zeroing
    dim3 gsw(HC * HC / 256, 1, 4);
    k_splitw<<<gsw, 256>>>(P[7], P[9], P[14], P[16]);

    // CSR
    k_count<<<(EE + 255) / 256, 256>>>(dst);
    k_scan<<<1, 1024>>>();
    k_scatter<<<(ET + 255) / 256, 256>>>(src, dst);
    k_slmean<<<(NN * 32 + 255) / 256, 256>>>(eattr);

    dim3 gg((NN + BM - 1) / BM, HC / BN, 2);
    dim3 gm((NN + GBM - 1) / GBM, HC / GBN, 2);

    // layer 0 (K=16, input = x)
    k_gemm<<<gg, 256>>>(x, P[0], P[1], P[2], P[3]);
    k_attn<<<(NN * 32 + 127) / 128, 128>>>(eattr, P[4], P[5], P[6]);
    // layer 1 (K=256)
    k_gemm_mma<<<gm, 256, SMEM_MMA>>>(0, P[8], P[10]);
    k_attn<<<(NN * 32 + 127) / 128, 128>>>(eattr, P[11], P[12], P[13]);
    // layer 2
    k_gemm_mma<<<gm, 256, SMEM_MMA>>>(2, P[15], P[17]);
    k_attn<<<(NN * 32 + 127) / 128, 128>>>(eattr, P[18], P[19], P[20]);

    // MLP head
    k_mlp<<<(NN * 32 + 255) / 256, 256>>>(P[21], P[22], P[23], P[24],
                                          P[25], P[26], P[27], P[28], out);
}